// round 3
// baseline (speedup 1.0000x reference)
#include <cuda_runtime.h>
#include <cuda_bf16.h>
#include <cstdint>

#define Vn 30000
#define Kn 17
#define En 128
#define Hn 128
#define Bn 128
#define Tn 512
#define G4H 512   // 4*H

// ---------------- scratch (device globals; allocation-free) ----------------
__device__ float g_xp[(size_t)2 * Tn * Bn * G4H];   // [dir][t][b][512]  (dir=1 time-reversed)
__device__ float g_hs[(size_t)Tn * Bn * 2 * Hn];    // [t][b][dir*128+j]
__device__ float g_em[(size_t)Bn * Tn * Kn];        // [b][t][k]
__device__ float g_llh[Bn];
__device__ __nv_bfloat16 g_embed_bf[(size_t)Vn * En];
__device__ __nv_bfloat16 g_wih_bf[2 * (size_t)G4H * En];  // [dir][g][k]
__device__ float g_bias[2 * G4H];

__device__ __forceinline__ float sigf(float x) { return 1.0f / (1.0f + __expf(-x)); }

// ================= Kernel 0: fp32 -> bf16 conversions =======================
__global__ __launch_bounds__(256) void k_cvt(
    const float* __restrict__ embed,
    const float* __restrict__ wf, const float* __restrict__ wb,
    const float* __restrict__ bihf, const float* __restrict__ bhhf,
    const float* __restrict__ bihb, const float* __restrict__ bhhb)
{
    int i = blockIdx.x * 256 + threadIdx.x;
    if (i < Vn * En / 2) {
        float2 v = ((const float2*)embed)[i];
        ((__nv_bfloat162*)g_embed_bf)[i] = __floats2bfloat162_rn(v.x, v.y);
    }
    if (i < G4H * En / 2) {
        float2 v = ((const float2*)wf)[i];
        ((__nv_bfloat162*)g_wih_bf)[i] = __floats2bfloat162_rn(v.x, v.y);
        float2 u = ((const float2*)wb)[i];
        ((__nv_bfloat162*)g_wih_bf)[G4H * En / 2 + i] = __floats2bfloat162_rn(u.x, u.y);
    }
    if (i < G4H) {
        g_bias[i] = bihf[i] + bhhf[i];
        g_bias[G4H + i] = bihb[i] + bhhb[i];
    }
}

// ================= Kernel 1: input projection via tensor cores ==============
// xp[dir][trow][b][g] = embed_bf[ids[b,t]] . wih_bf[dir][g,:] + bias[dir][g]
// One CTA = one timestep t (128 b-rows) x 128 g-cols. K=128 whole.
__device__ __forceinline__ uint32_t smaddr(const void* p) {
    return (uint32_t)__cvta_generic_to_shared(p);
}
__device__ __forceinline__ void ldm4(uint32_t& r0, uint32_t& r1, uint32_t& r2, uint32_t& r3, uint32_t a) {
    asm volatile("ldmatrix.sync.aligned.m8n8.x4.shared.b16 {%0,%1,%2,%3},[%4];"
                 : "=r"(r0), "=r"(r1), "=r"(r2), "=r"(r3) : "r"(a));
}
__device__ __forceinline__ void mma16816(float* c, uint32_t a0, uint32_t a1, uint32_t a2, uint32_t a3,
                                         uint32_t b0, uint32_t b1) {
    asm volatile("mma.sync.aligned.m16n8k16.row.col.f32.bf16.bf16.f32 "
                 "{%0,%1,%2,%3},{%4,%5,%6,%7},{%8,%9},{%0,%1,%2,%3};"
                 : "+f"(c[0]), "+f"(c[1]), "+f"(c[2]), "+f"(c[3])
                 : "r"(a0), "r"(a1), "r"(a2), "r"(a3), "r"(b0), "r"(b1));
}

#define ASTR 136   // bf16 elems per smem row (128 + 8 pad: conflict-free ldmatrix)

__global__ __launch_bounds__(256) void k_xp2(const int* __restrict__ ids)
{
    extern __shared__ char sm[];
    __nv_bfloat16* As = (__nv_bfloat16*)sm;                      // [128][136]
    __nv_bfloat16* Bs = (__nv_bfloat16*)(sm + 128 * ASTR * 2);   // [128][136]
    float* sbias = (float*)(sm + 2 * 128 * ASTR * 2);            // [128]

    const int t = blockIdx.x;          // M tile == timestep
    const int nt = blockIdx.y;         // 0..7
    const int dir = nt >> 2;
    const int gBase = (nt & 3) * 128;
    const int tid = threadIdx.x;

    // ---- load A (gathered embed rows, bf16) and B (w_ih rows, bf16) ----
    {
        int r = tid >> 1, half = tid & 1;
        int id = ids[r * Tn + t];
        const uint4* src = (const uint4*)(g_embed_bf + (size_t)id * En + half * 64);
        uint4* dst = (uint4*)(As + r * ASTR + half * 64);
#pragma unroll
        for (int i = 0; i < 8; i++) dst[i] = src[i];
        const uint4* wsrc = (const uint4*)(g_wih_bf + ((size_t)dir * G4H + gBase + r) * En + half * 64);
        uint4* wdst = (uint4*)(Bs + r * ASTR + half * 64);
#pragma unroll
        for (int i = 0; i < 8; i++) wdst[i] = wsrc[i];
    }
    if (tid < 128) sbias[tid] = g_bias[dir * G4H + gBase + tid];
    __syncthreads();

    const int wid = tid >> 5, lane = tid & 31;
    const int wm = (wid & 3) * 32;    // warp m offset (2 m16 tiles)
    const int wn = (wid >> 2) * 64;   // warp n offset (8 n8 tiles)

    float acc[2][8][4];
#pragma unroll
    for (int im = 0; im < 2; im++)
#pragma unroll
        for (int inn = 0; inn < 8; inn++)
#pragma unroll
            for (int r = 0; r < 4; r++) acc[im][inn][r] = 0.0f;

    const int lr = lane & 15, lc = lane >> 4;
#pragma unroll
    for (int kk = 0; kk < 8; kk++) {
        uint32_t a[2][4];
#pragma unroll
        for (int im = 0; im < 2; im++) {
            uint32_t ad = smaddr(As + (wm + im * 16 + lr) * ASTR + kk * 16 + lc * 8);
            ldm4(a[im][0], a[im][1], a[im][2], a[im][3], ad);
        }
        uint32_t b[4][4];
#pragma unroll
        for (int np = 0; np < 4; np++) {
            uint32_t ad = smaddr(Bs + (wn + np * 16 + lr) * ASTR + kk * 16 + lc * 8);
            ldm4(b[np][0], b[np][1], b[np][2], b[np][3], ad);
        }
#pragma unroll
        for (int im = 0; im < 2; im++)
#pragma unroll
            for (int inn = 0; inn < 8; inn++) {
                int np = inn >> 1, hf = inn & 1;
                // x4 tiles: m0=rows0-7/k0-7, m1=rows8-15/k0-7, m2=rows0-7/k8-15, m3=rows8-15/k8-15
                uint32_t bb0 = hf ? b[np][1] : b[np][0];
                uint32_t bb1 = hf ? b[np][3] : b[np][2];
                mma16816(acc[im][inn], a[im][0], a[im][1], a[im][2], a[im][3], bb0, bb1);
            }
    }

    // ---- epilogue: bias + store (time-reversed row for dir=1) ----
    const int trow = dir ? (Tn - 1 - t) : t;
    float* outBase = g_xp + (((size_t)dir * Tn + trow) * Bn) * G4H;
#pragma unroll
    for (int im = 0; im < 2; im++)
#pragma unroll
        for (int inn = 0; inn < 8; inn++) {
            int gl = wn + inn * 8 + 2 * (lane & 3);
            float bx = sbias[gl], by = sbias[gl + 1];
            int row0 = wm + im * 16 + (lane >> 2);
            float2 v0 = {acc[im][inn][0] + bx, acc[im][inn][1] + by};
            float2 v1 = {acc[im][inn][2] + bx, acc[im][inn][3] + by};
            *(float2*)(outBase + (size_t)row0 * G4H + gBase + gl) = v0;
            *(float2*)(outBase + (size_t)(row0 + 8) * G4H + gBase + gl) = v1;
        }
}

// ================= Kernel 2: BiLSTM recurrence ==============================
// 128 CTAs = (dir, batch-pair). W_hh rows live in REGISTERS as bf16x2 (64 regs).
// Inner product uses fma.rn.f32x2 with k-pair packing: acc.lo = even-k sum,
// acc.hi = odd-k sum. h is broadcast-read from smem as 16B vectors.
__device__ __forceinline__ unsigned long long wpair(uint32_t p) {
    unsigned long long r;
    asm("{\n\t.reg .b32 lo,hi;\n\t"
        "shl.b32 lo,%1,16;\n\t"
        "and.b32 hi,%1,0xffff0000;\n\t"
        "mov.b64 %0,{lo,hi};\n\t}" : "=l"(r) : "r"(p));
    return r;
}
__device__ __forceinline__ unsigned long long ffma2(unsigned long long a, unsigned long long b,
                                                    unsigned long long c) {
    unsigned long long d;
    asm("fma.rn.f32x2 %0,%1,%2,%3;" : "=l"(d) : "l"(a), "l"(b), "l"(c));
    return d;
}
__device__ __forceinline__ float pairsum(unsigned long long a, unsigned long long b) {
    unsigned long long s;
    asm("add.rn.f32x2 %0,%1,%2;" : "=l"(s) : "l"(a), "l"(b));
    uint32_t lo = (uint32_t)s, hi = (uint32_t)(s >> 32);
    return __uint_as_float(lo) + __uint_as_float(hi);
}
__device__ __forceinline__ unsigned long long mk2(float lo, float hi) {
    unsigned long long r;
    asm("mov.b64 %0,{%1,%2};" : "=l"(r) : "f"(lo), "f"(hi));
    return r;
}

__global__ __launch_bounds__(512, 1) void k_lstm(
    const float* __restrict__ whhf, const float* __restrict__ whhb)
{
    __shared__ float Hs[256];    // [bl][j] current h
    __shared__ float Gs[1024];   // [bl][g] gate preactivations

    const int blk = blockIdx.x;
    const int dir = blk >> 6;
    const int b0 = (blk & 63) * 2;
    const float* whh = dir ? whhb : whhf;
    const int tid = threadIdx.x;

    // W_hh row g=tid -> 64 bf16x2 registers
    uint32_t wreg[64];
    {
        const float2* wrow = (const float2*)(whh + (size_t)tid * Hn);
#pragma unroll
        for (int r = 0; r < 64; r++) {
            float2 w2 = wrow[r];
            __nv_bfloat162 p = __floats2bfloat162_rn(w2.x, w2.y);
            wreg[r] = *(uint32_t*)&p;
        }
    }
    if (tid < 256) Hs[tid] = 0.0f;
    float c = 0.0f;
    const int bl = tid >> 7, j = tid & 127;
    __syncthreads();

    const size_t stepStride = (size_t)Bn * G4H;
    const float* xp0 = g_xp + (size_t)dir * Tn * Bn * G4H + (size_t)b0 * G4H + tid;
    const float* xp1 = xp0 + G4H;
    float nx0 = xp0[0], nx1 = xp1[0];

    for (int t = 0; t < Tn; t++) {
        unsigned long long a0a = mk2(nx0, 0.0f), a0b = mk2(0.0f, 0.0f);
        unsigned long long a1a = mk2(nx1, 0.0f), a1b = mk2(0.0f, 0.0f);
        if (t + 1 < Tn) {
            nx0 = xp0[(size_t)(t + 1) * stepStride];
            nx1 = xp1[(size_t)(t + 1) * stepStride];
        }
        const ulonglong2* H0 = (const ulonglong2*)Hs;         // 32 x 16B
        const ulonglong2* H1 = (const ulonglong2*)(Hs + 128);
#pragma unroll
        for (int q = 0; q < 32; q += 2) {
            ulonglong2 p00 = H0[q], p01 = H0[q + 1];
            ulonglong2 p10 = H1[q], p11 = H1[q + 1];
            unsigned long long w0 = wpair(wreg[2 * q]);
            a0a = ffma2(w0, p00.x, a0a);
            a1a = ffma2(w0, p10.x, a1a);
            unsigned long long w1 = wpair(wreg[2 * q + 1]);
            a0a = ffma2(w1, p00.y, a0a);
            a1a = ffma2(w1, p10.y, a1a);
            unsigned long long w2 = wpair(wreg[2 * q + 2]);
            a0b = ffma2(w2, p01.x, a0b);
            a1b = ffma2(w2, p11.x, a1b);
            unsigned long long w3 = wpair(wreg[2 * q + 3]);
            a0b = ffma2(w3, p01.y, a0b);
            a1b = ffma2(w3, p11.y, a1b);
        }
        Gs[tid] = pairsum(a0a, a0b);
        Gs[512 + tid] = pairsum(a1a, a1b);
        __syncthreads();
        if (tid < 256) {
            float gi = Gs[bl * 512 + j];
            float gf = Gs[bl * 512 + 128 + j];
            float gg = Gs[bl * 512 + 256 + j];
            float go = Gs[bl * 512 + 384 + j];
            c = sigf(gf) * c + sigf(gi) * tanhf(gg);
            float h = sigf(go) * tanhf(c);
            Hs[bl * 128 + j] = h;
            int trow = dir ? (Tn - 1 - t) : t;
            g_hs[((size_t)trow * Bn + (b0 + bl)) * (2 * Hn) + dir * Hn + j] = h;
        }
        __syncthreads();
    }
}

// ================= Kernel 3: emissions ======================================
__global__ __launch_bounds__(544) void k_emit(
    const float* __restrict__ w_emit, const float* __restrict__ b_emit)
{
    __shared__ float ws[Kn * 257];
    const int tid = threadIdx.x;
    for (int i = tid; i < Kn * 256; i += 544)
        ws[(i >> 8) * 257 + (i & 255)] = w_emit[i];
    __syncthreads();

    const int kk = tid % 17;
    const int blc = tid / 17;
    const int bt = blockIdx.x * 32 + blc;   // bt = t*B + b
    const int t = bt >> 7, b = bt & 127;

    const float4* hv = (const float4*)(g_hs + (size_t)bt * 256);
    const float* wr = &ws[kk * 257];
    float dot = 0.0f;
#pragma unroll 8
    for (int i = 0; i < 64; i++) {
        float4 h4 = hv[i];
        dot += h4.x * wr[i * 4 + 0] + h4.y * wr[i * 4 + 1]
             + h4.z * wr[i * 4 + 2] + h4.w * wr[i * 4 + 3];
    }
    g_em[((size_t)b * Tn + t) * Kn + kk] = dot + b_emit[kk];
}

// ================= Kernel 4: CRF, two interleaved batches per warp ==========
__global__ void k_crf(const int* __restrict__ tags,
                      const float* __restrict__ start_t,
                      const float* __restrict__ end_t,
                      const float* __restrict__ trans)
{
    const int lane = threadIdx.x;
    const int bA = blockIdx.x, bB = blockIdx.x + 64;
    const float* emA = g_em + (size_t)bA * Tn * Kn;
    const float* emB = g_em + (size_t)bB * Tn * Kn;

    float tcol[Kn];
#pragma unroll
    for (int i = 0; i < Kn; i++)
        tcol[i] = (lane < Kn) ? trans[i * Kn + lane] : 0.0f;

    float alA = (lane < Kn) ? (start_t[lane] + emA[lane]) : -1e30f;
    float alB = (lane < Kn) ? (start_t[lane] + emB[lane]) : -1e30f;

    int tpA = tags[bA * Tn], tpB = tags[bB * Tn];
    float scA = start_t[tpA] + emA[tpA];
    float scB = start_t[tpB] + emB[tpB];

    const int laneC = (lane < Kn) ? lane : 0;
    float ecA = emA[Kn + laneC], ecB = emB[Kn + laneC];
    int tcA = tags[bA * Tn + 1], tcB = tags[bB * Tn + 1];

    for (int t = 1; t < Tn; t++) {
        float enA = 0.0f, enB = 0.0f;
        int tnA = 0, tnB = 0;
        if (t + 1 < Tn) {
            enA = emA[(size_t)(t + 1) * Kn + laneC];
            tnA = tags[bA * Tn + t + 1];
            enB = emB[(size_t)(t + 1) * Kn + laneC];
            tnB = tags[bB * Tn + t + 1];
        }
        float vA[Kn], vB[Kn];
        float mA = -1e30f, mB = -1e30f;
#pragma unroll
        for (int i = 0; i < Kn; i++) {
            float aiA = __shfl_sync(0xffffffffu, alA, i);
            float aiB = __shfl_sync(0xffffffffu, alB, i);
            vA[i] = aiA + tcol[i];
            vB[i] = aiB + tcol[i];
            mA = fmaxf(mA, vA[i]);
            mB = fmaxf(mB, vB[i]);
        }
        float sA = 0.0f, sB = 0.0f;
#pragma unroll
        for (int i = 0; i < Kn; i++) {
            sA += __expf(vA[i] - mA);
            sB += __expf(vB[i] - mB);
        }
        float naA = mA + __logf(sA) + ecA;
        float naB = mB + __logf(sB) + ecB;
        if (lane < Kn) { alA = naA; alB = naB; }

        scA += trans[tpA * Kn + tcA] + emA[(size_t)t * Kn + tcA];
        scB += trans[tpB * Kn + tcB] + emB[(size_t)t * Kn + tcB];
        tpA = tcA; tpB = tcB;
        ecA = enA; ecB = enB; tcA = tnA; tcB = tnB;
    }
    scA += end_t[tpA];
    scB += end_t[tpB];

    float xA = (lane < Kn) ? (alA + end_t[lane]) : -1e30f;
    float xB = (lane < Kn) ? (alB + end_t[lane]) : -1e30f;
    float mA = xA, mB = xB;
#pragma unroll
    for (int off = 16; off; off >>= 1) {
        mA = fmaxf(mA, __shfl_xor_sync(0xffffffffu, mA, off));
        mB = fmaxf(mB, __shfl_xor_sync(0xffffffffu, mB, off));
    }
    float sA = __expf(xA - mA), sB = __expf(xB - mB);
#pragma unroll
    for (int off = 16; off; off >>= 1) {
        sA += __shfl_xor_sync(0xffffffffu, sA, off);
        sB += __shfl_xor_sync(0xffffffffu, sB, off);
    }
    if (lane == 0) {
        g_llh[bA] = scA - (mA + __logf(sA));
        g_llh[bB] = scB - (mB + __logf(sB));
    }
}

// ================= Kernel 5: final mean =====================================
__global__ void k_reduce(float* __restrict__ out)
{
    const int tid = threadIdx.x; // 128
    float v = g_llh[tid];
#pragma unroll
    for (int off = 16; off; off >>= 1) v += __shfl_xor_sync(0xffffffffu, v, off);
    __shared__ float s[4];
    if ((tid & 31) == 0) s[tid >> 5] = v;
    __syncthreads();
    if (tid == 0) out[0] = -(s[0] + s[1] + s[2] + s[3]) / (float)Bn;
}

// ============================================================================
extern "C" void kernel_launch(void* const* d_in, const int* in_sizes, int n_in,
                              void* d_out, int out_size)
{
    const int*   ids     = (const int*)d_in[0];
    const int*   tags    = (const int*)d_in[1];
    // d_in[2] = mask: all-true for this problem; intentionally unused.
    const float* embed   = (const float*)d_in[3];
    const float* w_ih_f  = (const float*)d_in[4];
    const float* w_hh_f  = (const float*)d_in[5];
    const float* b_ih_f  = (const float*)d_in[6];
    const float* b_hh_f  = (const float*)d_in[7];
    const float* w_ih_b  = (const float*)d_in[8];
    const float* w_hh_b  = (const float*)d_in[9];
    const float* b_ih_b  = (const float*)d_in[10];
    const float* b_hh_b  = (const float*)d_in[11];
    const float* w_emit  = (const float*)d_in[12];
    const float* b_emit  = (const float*)d_in[13];
    const float* start_t = (const float*)d_in[14];
    const float* end_t   = (const float*)d_in[15];
    const float* trans   = (const float*)d_in[16];

    const int SMEM_XP2 = 2 * 128 * ASTR * 2 + 512;   // 70,144 B
    cudaFuncSetAttribute(k_xp2, cudaFuncAttributeMaxDynamicSharedMemorySize, SMEM_XP2);

    k_cvt<<<Vn * En / 2 / 256, 256>>>(embed, w_ih_f, w_ih_b,
                                      b_ih_f, b_hh_f, b_ih_b, b_hh_b);
    k_xp2<<<dim3(512, 8), 256, SMEM_XP2>>>(ids);
    k_lstm<<<128, 512>>>(w_hh_f, w_hh_b);
    k_emit<<<2048, 544>>>(w_emit, b_emit);
    k_crf<<<64, 32>>>(tags, start_t, end_t, trans);
    k_reduce<<<1, 128>>>((float*)d_out);
}

// round 4
// speedup vs baseline: 1.8672x; 1.8672x over previous
#include <cuda_runtime.h>
#include <cuda_bf16.h>
#include <cstdint>

#define Vn 30000
#define Kn 17
#define En 128
#define Hn 128
#define Bn 128
#define Tn 512
#define G4H 512   // 4*H

// ---------------- scratch (device globals; allocation-free) ----------------
__device__ float g_xp[(size_t)2 * Tn * Bn * G4H];   // [dir][t][b][512]  (dir=1 time-reversed)
__device__ float g_hs[(size_t)Tn * Bn * 2 * Hn];    // [t][b][dir*128+j]
__device__ float g_em[(size_t)Bn * Tn * Kn];        // [b][t][k]
__device__ float g_llh[Bn];
__device__ __nv_bfloat16 g_embed_bf[(size_t)Vn * En];
__device__ __nv_bfloat16 g_wih_bf[2 * (size_t)G4H * En];  // [dir][g][k]
__device__ float g_bias[2 * G4H];

__device__ __forceinline__ float tanha(float x) {
    float r; asm("tanh.approx.f32 %0,%1;" : "=f"(r) : "f"(x)); return r;
}
__device__ __forceinline__ float siga(float x) {
    return 0.5f * tanha(0.5f * x) + 0.5f;
}

// ================= Kernel 0: fp32 -> bf16 conversions =======================
__global__ __launch_bounds__(256) void k_cvt(
    const float* __restrict__ embed,
    const float* __restrict__ wf, const float* __restrict__ wb,
    const float* __restrict__ bihf, const float* __restrict__ bhhf,
    const float* __restrict__ bihb, const float* __restrict__ bhhb)
{
    int i = blockIdx.x * 256 + threadIdx.x;
    if (i < Vn * En / 2) {
        float2 v = ((const float2*)embed)[i];
        ((__nv_bfloat162*)g_embed_bf)[i] = __floats2bfloat162_rn(v.x, v.y);
    }
    if (i < G4H * En / 2) {
        float2 v = ((const float2*)wf)[i];
        ((__nv_bfloat162*)g_wih_bf)[i] = __floats2bfloat162_rn(v.x, v.y);
        float2 u = ((const float2*)wb)[i];
        ((__nv_bfloat162*)g_wih_bf)[G4H * En / 2 + i] = __floats2bfloat162_rn(u.x, u.y);
    }
    if (i < G4H) {
        g_bias[i] = bihf[i] + bhhf[i];
        g_bias[G4H + i] = bihb[i] + bhhb[i];
    }
}

// ---------------- mma helpers ----------------
__device__ __forceinline__ uint32_t smaddr(const void* p) {
    return (uint32_t)__cvta_generic_to_shared(p);
}
__device__ __forceinline__ void ldm4(uint32_t& r0, uint32_t& r1, uint32_t& r2, uint32_t& r3, uint32_t a) {
    asm volatile("ldmatrix.sync.aligned.m8n8.x4.shared.b16 {%0,%1,%2,%3},[%4];"
                 : "=r"(r0), "=r"(r1), "=r"(r2), "=r"(r3) : "r"(a));
}
__device__ __forceinline__ void mma16816(float* c, uint32_t a0, uint32_t a1, uint32_t a2, uint32_t a3,
                                         uint32_t b0, uint32_t b1) {
    asm volatile("mma.sync.aligned.m16n8k16.row.col.f32.bf16.bf16.f32 "
                 "{%0,%1,%2,%3},{%4,%5,%6,%7},{%8,%9},{%0,%1,%2,%3};"
                 : "+f"(c[0]), "+f"(c[1]), "+f"(c[2]), "+f"(c[3])
                 : "r"(a0), "r"(a1), "r"(a2), "r"(a3), "r"(b0), "r"(b1));
}

#define ASTR 136   // bf16 elems per smem row (128 + 8 pad: conflict-free ldmatrix)

// ================= Kernel 1: input projection via tensor cores ==============
__global__ __launch_bounds__(256) void k_xp2(const int* __restrict__ ids)
{
    extern __shared__ char sm[];
    __nv_bfloat16* As = (__nv_bfloat16*)sm;                      // [128][136]
    __nv_bfloat16* Bs = (__nv_bfloat16*)(sm + 128 * ASTR * 2);   // [128][136]
    float* sbias = (float*)(sm + 2 * 128 * ASTR * 2);            // [128]

    const int t = blockIdx.x;          // M tile == timestep
    const int nt = blockIdx.y;         // 0..7
    const int dir = nt >> 2;
    const int gBase = (nt & 3) * 128;
    const int tid = threadIdx.x;

    {
        int r = tid >> 1, half = tid & 1;
        int id = ids[r * Tn + t];
        const uint4* src = (const uint4*)(g_embed_bf + (size_t)id * En + half * 64);
        uint4* dst = (uint4*)(As + r * ASTR + half * 64);
#pragma unroll
        for (int i = 0; i < 8; i++) dst[i] = src[i];
        const uint4* wsrc = (const uint4*)(g_wih_bf + ((size_t)dir * G4H + gBase + r) * En + half * 64);
        uint4* wdst = (uint4*)(Bs + r * ASTR + half * 64);
#pragma unroll
        for (int i = 0; i < 8; i++) wdst[i] = wsrc[i];
    }
    if (tid < 128) sbias[tid] = g_bias[dir * G4H + gBase + tid];
    __syncthreads();

    const int wid = tid >> 5, lane = tid & 31;
    const int wm = (wid & 3) * 32;
    const int wn = (wid >> 2) * 64;

    float acc[2][8][4];
#pragma unroll
    for (int im = 0; im < 2; im++)
#pragma unroll
        for (int inn = 0; inn < 8; inn++)
#pragma unroll
            for (int r = 0; r < 4; r++) acc[im][inn][r] = 0.0f;

    const int lr = lane & 15, lc = lane >> 4;
#pragma unroll
    for (int kk = 0; kk < 8; kk++) {
        uint32_t a[2][4];
#pragma unroll
        for (int im = 0; im < 2; im++) {
            uint32_t ad = smaddr(As + (wm + im * 16 + lr) * ASTR + kk * 16 + lc * 8);
            ldm4(a[im][0], a[im][1], a[im][2], a[im][3], ad);
        }
        uint32_t b[4][4];
#pragma unroll
        for (int np = 0; np < 4; np++) {
            uint32_t ad = smaddr(Bs + (wn + np * 16 + lr) * ASTR + kk * 16 + lc * 8);
            ldm4(b[np][0], b[np][1], b[np][2], b[np][3], ad);
        }
#pragma unroll
        for (int im = 0; im < 2; im++)
#pragma unroll
            for (int inn = 0; inn < 8; inn++) {
                int np = inn >> 1, hf = inn & 1;
                uint32_t bb0 = hf ? b[np][1] : b[np][0];
                uint32_t bb1 = hf ? b[np][3] : b[np][2];
                mma16816(acc[im][inn], a[im][0], a[im][1], a[im][2], a[im][3], bb0, bb1);
            }
    }

    const int trow = dir ? (Tn - 1 - t) : t;
    float* outBase = g_xp + (((size_t)dir * Tn + trow) * Bn) * G4H;
#pragma unroll
    for (int im = 0; im < 2; im++)
#pragma unroll
        for (int inn = 0; inn < 8; inn++) {
            int gl = wn + inn * 8 + 2 * (lane & 3);
            float bx = sbias[gl], by = sbias[gl + 1];
            int row0 = wm + im * 16 + (lane >> 2);
            float2 v0 = {acc[im][inn][0] + bx, acc[im][inn][1] + by};
            float2 v1 = {acc[im][inn][2] + bx, acc[im][inn][3] + by};
            *(float2*)(outBase + (size_t)row0 * G4H + gBase + gl) = v0;
            *(float2*)(outBase + (size_t)(row0 + 8) * G4H + gBase + gl) = v1;
        }
}

// ================= Kernel 2: tensor-core BiLSTM recurrence ==================
// 32 CTAs = (dir, 8-batch group). Per step: gates[8x512] = xp + h@W_hh^T via
// mma.m16n8k16 (m16 with 8 zero rows). W_hh bf16 in smem (139KB), h bf16 in
// smem, c in registers. 256 threads = 8 warps; warp w owns gate cols
// [w*64, w*64+64) for the GEMM and batch row w for the pointwise epilogue.
#define GSTR 516

__global__ __launch_bounds__(256, 1) void k_lstm3(
    const float* __restrict__ whhf, const float* __restrict__ whhb)
{
    extern __shared__ char smraw[];
    __nv_bfloat16* Wsm = (__nv_bfloat16*)smraw;                       // [512][136]
    __nv_bfloat16* Hsm = (__nv_bfloat16*)(smraw + 512 * ASTR * 2);    // [16][136]
    float* Gs = (float*)(smraw + 512 * ASTR * 2 + 16 * ASTR * 2);     // [8][516]

    const int dir = blockIdx.x >> 4;
    const int b0 = (blockIdx.x & 15) * 8;
    const float* whh = dir ? whhb : whhf;
    const int tid = threadIdx.x;
    const int wid = tid >> 5, lane = tid & 31;
    const int wn = wid * 64;

    // ---- load W_hh -> smem bf16 (2 rows per thread) ----
    {
#pragma unroll
        for (int rr = 0; rr < 2; rr++) {
            int row = tid * 2 + rr;
            const float2* src = (const float2*)(whh + (size_t)row * Hn);
            __nv_bfloat162* dst = (__nv_bfloat162*)(Wsm + row * ASTR);
#pragma unroll 8
            for (int i = 0; i < 64; i++) {
                float2 v = src[i];
                dst[i] = __floats2bfloat162_rn(v.x, v.y);
            }
        }
    }
    // zero h (all 16 rows incl. 8 pad rows)
    for (int i = tid; i < 16 * ASTR / 2; i += 256) ((uint32_t*)Hsm)[i] = 0u;
    __syncthreads();

    const int lr = lane & 15, lc = lane >> 4;
    const int row0 = lane >> 2;            // mma acc row (0..7 real)
    const int col2 = 2 * (lane & 3);       // mma acc col pair offset

    // per-thread xp pointer: (dir, b0+row0, wn+col2), advances over t
    const float* xpt = g_xp + (size_t)dir * Tn * Bn * G4H
                      + (size_t)(b0 + row0) * G4H + wn + col2;
    const size_t tstride = (size_t)Bn * G4H;

    float2 xpc[8], xpn[8];
#pragma unroll
    for (int inn = 0; inn < 8; inn++) xpc[inn] = *(const float2*)(xpt + inn * 8);

    float creg[4] = {0.f, 0.f, 0.f, 0.f};   // c for (b=wid, j=lane*4..+3)
    const int j0 = lane * 4;

    for (int t = 0; t < Tn; t++) {
        // prefetch next xp
        if (t + 1 < Tn) {
            const float* p = xpt + (size_t)(t + 1) * tstride;
#pragma unroll
            for (int inn = 0; inn < 8; inn++) xpn[inn] = *(const float2*)(p + inn * 8);
        }
        // acc init from xp
        float acc[8][4];
#pragma unroll
        for (int inn = 0; inn < 8; inn++) {
            acc[inn][0] = xpc[inn].x;
            acc[inn][1] = xpc[inn].y;
            acc[inn][2] = 0.0f;
            acc[inn][3] = 0.0f;
        }
        // GEMM: gates += h @ W_hh^T
#pragma unroll
        for (int kk = 0; kk < 8; kk++) {
            uint32_t a0, a1, a2, a3;
            ldm4(a0, a1, a2, a3, smaddr(Hsm + lr * ASTR + kk * 16 + lc * 8));
            uint32_t b[4][4];
#pragma unroll
            for (int np = 0; np < 4; np++) {
                uint32_t ad = smaddr(Wsm + (wn + np * 16 + lr) * ASTR + kk * 16 + lc * 8);
                ldm4(b[np][0], b[np][1], b[np][2], b[np][3], ad);
            }
#pragma unroll
            for (int inn = 0; inn < 8; inn++) {
                int np = inn >> 1, hf = inn & 1;
                uint32_t bb0 = hf ? b[np][1] : b[np][0];
                uint32_t bb1 = hf ? b[np][3] : b[np][2];
                mma16816(acc[inn], a0, a1, a2, a3, bb0, bb1);
            }
        }
        // scatter gates to smem (real rows only)
#pragma unroll
        for (int inn = 0; inn < 8; inn++) {
            float2 v = {acc[inn][0], acc[inn][1]};
            *(float2*)&Gs[row0 * GSTR + wn + inn * 8 + col2] = v;
        }
        __syncthreads();

        // ---- pointwise: warp w = batch row w, lane = j block of 4 ----
        {
            const float* gb = &Gs[wid * GSTR];
            float4 gi = *(const float4*)&gb[j0];
            float4 gf = *(const float4*)&gb[128 + j0];
            float4 gg = *(const float4*)&gb[256 + j0];
            float4 go = *(const float4*)&gb[384 + j0];
            float h[4];
            creg[0] = siga(gf.x) * creg[0] + siga(gi.x) * tanha(gg.x);
            creg[1] = siga(gf.y) * creg[1] + siga(gi.y) * tanha(gg.y);
            creg[2] = siga(gf.z) * creg[2] + siga(gi.z) * tanha(gg.z);
            creg[3] = siga(gf.w) * creg[3] + siga(gi.w) * tanha(gg.w);
            h[0] = siga(go.x) * tanha(creg[0]);
            h[1] = siga(go.y) * tanha(creg[1]);
            h[2] = siga(go.z) * tanha(creg[2]);
            h[3] = siga(go.w) * tanha(creg[3]);

            // h -> smem bf16 (for next step's A)
            __nv_bfloat162 p0 = __floats2bfloat162_rn(h[0], h[1]);
            __nv_bfloat162 p1 = __floats2bfloat162_rn(h[2], h[3]);
            uint2 pk = {*(uint32_t*)&p0, *(uint32_t*)&p1};
            *(uint2*)(Hsm + wid * ASTR + j0) = pk;

            // h -> global fp32
            int trow = dir ? (Tn - 1 - t) : t;
            float4 hv = {h[0], h[1], h[2], h[3]};
            *(float4*)(g_hs + ((size_t)trow * Bn + (b0 + wid)) * (2 * Hn) + dir * Hn + j0) = hv;
        }
        __syncthreads();

#pragma unroll
        for (int inn = 0; inn < 8; inn++) xpc[inn] = xpn[inn];
    }
}

// ================= Kernel 3: emissions ======================================
__global__ __launch_bounds__(544) void k_emit(
    const float* __restrict__ w_emit, const float* __restrict__ b_emit)
{
    __shared__ float ws[Kn * 257];
    const int tid = threadIdx.x;
    for (int i = tid; i < Kn * 256; i += 544)
        ws[(i >> 8) * 257 + (i & 255)] = w_emit[i];
    __syncthreads();

    const int kk = tid % 17;
    const int blc = tid / 17;
    const int bt = blockIdx.x * 32 + blc;   // bt = t*B + b
    const int t = bt >> 7, b = bt & 127;

    const float4* hv = (const float4*)(g_hs + (size_t)bt * 256);
    const float* wr = &ws[kk * 257];
    float dot = 0.0f;
#pragma unroll 8
    for (int i = 0; i < 64; i++) {
        float4 h4 = hv[i];
        dot += h4.x * wr[i * 4 + 0] + h4.y * wr[i * 4 + 1]
             + h4.z * wr[i * 4 + 2] + h4.w * wr[i * 4 + 3];
    }
    g_em[((size_t)b * Tn + t) * Kn + kk] = dot + b_emit[kk];
}

// ================= Kernel 4: CRF, two interleaved batches per warp ==========
__global__ void k_crf(const int* __restrict__ tags,
                      const float* __restrict__ start_t,
                      const float* __restrict__ end_t,
                      const float* __restrict__ trans)
{
    const int lane = threadIdx.x;
    const int bA = blockIdx.x, bB = blockIdx.x + 64;
    const float* emA = g_em + (size_t)bA * Tn * Kn;
    const float* emB = g_em + (size_t)bB * Tn * Kn;

    float tcol[Kn];
#pragma unroll
    for (int i = 0; i < Kn; i++)
        tcol[i] = (lane < Kn) ? trans[i * Kn + lane] : 0.0f;

    float alA = (lane < Kn) ? (start_t[lane] + emA[lane]) : -1e30f;
    float alB = (lane < Kn) ? (start_t[lane] + emB[lane]) : -1e30f;

    int tpA = tags[bA * Tn], tpB = tags[bB * Tn];
    float scA = start_t[tpA] + emA[tpA];
    float scB = start_t[tpB] + emB[tpB];

    const int laneC = (lane < Kn) ? lane : 0;
    float ecA = emA[Kn + laneC], ecB = emB[Kn + laneC];
    int tcA = tags[bA * Tn + 1], tcB = tags[bB * Tn + 1];

    for (int t = 1; t < Tn; t++) {
        float enA = 0.0f, enB = 0.0f;
        int tnA = 0, tnB = 0;
        if (t + 1 < Tn) {
            enA = emA[(size_t)(t + 1) * Kn + laneC];
            tnA = tags[bA * Tn + t + 1];
            enB = emB[(size_t)(t + 1) * Kn + laneC];
            tnB = tags[bB * Tn + t + 1];
        }
        float vA[Kn], vB[Kn];
        float mA = -1e30f, mB = -1e30f;
#pragma unroll
        for (int i = 0; i < Kn; i++) {
            float aiA = __shfl_sync(0xffffffffu, alA, i);
            float aiB = __shfl_sync(0xffffffffu, alB, i);
            vA[i] = aiA + tcol[i];
            vB[i] = aiB + tcol[i];
            mA = fmaxf(mA, vA[i]);
            mB = fmaxf(mB, vB[i]);
        }
        float sA = 0.0f, sB = 0.0f;
#pragma unroll
        for (int i = 0; i < Kn; i++) {
            sA += __expf(vA[i] - mA);
            sB += __expf(vB[i] - mB);
        }
        float naA = mA + __logf(sA) + ecA;
        float naB = mB + __logf(sB) + ecB;
        if (lane < Kn) { alA = naA; alB = naB; }

        scA += trans[tpA * Kn + tcA] + emA[(size_t)t * Kn + tcA];
        scB += trans[tpB * Kn + tcB] + emB[(size_t)t * Kn + tcB];
        tpA = tcA; tpB = tcB;
        ecA = enA; ecB = enB; tcA = tnA; tcB = tnB;
    }
    scA += end_t[tpA];
    scB += end_t[tpB];

    float xA = (lane < Kn) ? (alA + end_t[lane]) : -1e30f;
    float xB = (lane < Kn) ? (alB + end_t[lane]) : -1e30f;
    float mA = xA, mB = xB;
#pragma unroll
    for (int off = 16; off; off >>= 1) {
        mA = fmaxf(mA, __shfl_xor_sync(0xffffffffu, mA, off));
        mB = fmaxf(mB, __shfl_xor_sync(0xffffffffu, mB, off));
    }
    float sA = __expf(xA - mA), sB = __expf(xB - mB);
#pragma unroll
    for (int off = 16; off; off >>= 1) {
        sA += __shfl_xor_sync(0xffffffffu, sA, off);
        sB += __shfl_xor_sync(0xffffffffu, sB, off);
    }
    if (lane == 0) {
        g_llh[bA] = scA - (mA + __logf(sA));
        g_llh[bB] = scB - (mB + __logf(sB));
    }
}

// ================= Kernel 5: final mean =====================================
__global__ void k_reduce(float* __restrict__ out)
{
    const int tid = threadIdx.x; // 128
    float v = g_llh[tid];
#pragma unroll
    for (int off = 16; off; off >>= 1) v += __shfl_xor_sync(0xffffffffu, v, off);
    __shared__ float s[4];
    if ((tid & 31) == 0) s[tid >> 5] = v;
    __syncthreads();
    if (tid == 0) out[0] = -(s[0] + s[1] + s[2] + s[3]) / (float)Bn;
}

// ============================================================================
extern "C" void kernel_launch(void* const* d_in, const int* in_sizes, int n_in,
                              void* d_out, int out_size)
{
    const int*   ids     = (const int*)d_in[0];
    const int*   tags    = (const int*)d_in[1];
    // d_in[2] = mask: all-true for this problem; intentionally unused.
    const float* embed   = (const float*)d_in[3];
    const float* w_ih_f  = (const float*)d_in[4];
    const float* w_hh_f  = (const float*)d_in[5];
    const float* b_ih_f  = (const float*)d_in[6];
    const float* b_hh_f  = (const float*)d_in[7];
    const float* w_ih_b  = (const float*)d_in[8];
    const float* w_hh_b  = (const float*)d_in[9];
    const float* b_ih_b  = (const float*)d_in[10];
    const float* b_hh_b  = (const float*)d_in[11];
    const float* w_emit  = (const float*)d_in[12];
    const float* b_emit  = (const float*)d_in[13];
    const float* start_t = (const float*)d_in[14];
    const float* end_t   = (const float*)d_in[15];
    const float* trans   = (const float*)d_in[16];

    const int SMEM_XP2   = 2 * 128 * ASTR * 2 + 512;                        // 70,144 B
    const int SMEM_LSTM3 = 512 * ASTR * 2 + 16 * ASTR * 2 + 8 * GSTR * 4;   // 160,128 B
    cudaFuncSetAttribute(k_xp2,   cudaFuncAttributeMaxDynamicSharedMemorySize, SMEM_XP2);
    cudaFuncSetAttribute(k_lstm3, cudaFuncAttributeMaxDynamicSharedMemorySize, SMEM_LSTM3);

    k_cvt<<<Vn * En / 2 / 256, 256>>>(embed, w_ih_f, w_ih_b,
                                      b_ih_f, b_hh_f, b_ih_b, b_hh_b);
    k_xp2<<<dim3(512, 8), 256, SMEM_XP2>>>(ids);
    k_lstm3<<<32, 256, SMEM_LSTM3>>>(w_hh_f, w_hh_b);
    k_emit<<<2048, 544>>>(w_emit, b_emit);
    k_crf<<<64, 32>>>(tags, start_t, end_t, trans);
    k_reduce<<<1, 128>>>((float*)d_out);
}

// round 5
// speedup vs baseline: 2.2519x; 1.2060x over previous
#include <cuda_runtime.h>
#include <cuda_bf16.h>
#include <cstdint>

#define Vn 30000
#define Kn 17
#define En 128
#define Hn 128
#define Bn 128
#define Tn 512
#define G4H 512   // 4*H

// ---------------- scratch (device globals; allocation-free) ----------------
__device__ float g_xp[(size_t)2 * Tn * Bn * G4H];   // [dir][t][b][512]  (dir=1 time-reversed)
__device__ float g_hs[(size_t)Tn * Bn * 2 * Hn];    // [t][b][dir*128+j]
__device__ float g_em[(size_t)Bn * Tn * Kn];        // [b][t][k]
__device__ float g_llh[Bn];
__device__ __nv_bfloat16 g_embed_bf[(size_t)Vn * En];
__device__ __nv_bfloat16 g_wih_bf[2 * (size_t)G4H * En];  // [dir][g][k]
__device__ float g_bias[2 * G4H];

__device__ __forceinline__ float tanha(float x) {
    float r; asm("tanh.approx.f32 %0,%1;" : "=f"(r) : "f"(x)); return r;
}
__device__ __forceinline__ float siga(float x) {
    return 0.5f * tanha(0.5f * x) + 0.5f;
}

// ================= Kernel 0: fp32 -> bf16 conversions =======================
__global__ __launch_bounds__(256) void k_cvt(
    const float* __restrict__ embed,
    const float* __restrict__ wf, const float* __restrict__ wb,
    const float* __restrict__ bihf, const float* __restrict__ bhhf,
    const float* __restrict__ bihb, const float* __restrict__ bhhb)
{
    int i = blockIdx.x * 256 + threadIdx.x;
    if (i < Vn * En / 2) {
        float2 v = ((const float2*)embed)[i];
        ((__nv_bfloat162*)g_embed_bf)[i] = __floats2bfloat162_rn(v.x, v.y);
    }
    if (i < G4H * En / 2) {
        float2 v = ((const float2*)wf)[i];
        ((__nv_bfloat162*)g_wih_bf)[i] = __floats2bfloat162_rn(v.x, v.y);
        float2 u = ((const float2*)wb)[i];
        ((__nv_bfloat162*)g_wih_bf)[G4H * En / 2 + i] = __floats2bfloat162_rn(u.x, u.y);
    }
    if (i < G4H) {
        g_bias[i] = bihf[i] + bhhf[i];
        g_bias[G4H + i] = bihb[i] + bhhb[i];
    }
}

// ---------------- mma / cluster helpers ----------------
__device__ __forceinline__ uint32_t smaddr(const void* p) {
    return (uint32_t)__cvta_generic_to_shared(p);
}
__device__ __forceinline__ void ldm4(uint32_t& r0, uint32_t& r1, uint32_t& r2, uint32_t& r3, uint32_t a) {
    asm volatile("ldmatrix.sync.aligned.m8n8.x4.shared.b16 {%0,%1,%2,%3},[%4];"
                 : "=r"(r0), "=r"(r1), "=r"(r2), "=r"(r3) : "r"(a));
}
__device__ __forceinline__ void mma16816(float* c, uint32_t a0, uint32_t a1, uint32_t a2, uint32_t a3,
                                         uint32_t b0, uint32_t b1) {
    asm volatile("mma.sync.aligned.m16n8k16.row.col.f32.bf16.bf16.f32 "
                 "{%0,%1,%2,%3},{%4,%5,%6,%7},{%8,%9},{%0,%1,%2,%3};"
                 : "+f"(c[0]), "+f"(c[1]), "+f"(c[2]), "+f"(c[3])
                 : "r"(a0), "r"(a1), "r"(a2), "r"(a3), "r"(b0), "r"(b1));
}
__device__ __forceinline__ uint32_t mapa_u32(uint32_t a, uint32_t rnk) {
    uint32_t d; asm("mapa.shared::cluster.u32 %0,%1,%2;" : "=r"(d) : "r"(a), "r"(rnk));
    return d;
}
__device__ __forceinline__ void mbar_init(uint32_t bar, uint32_t cnt) {
    asm volatile("mbarrier.init.shared.b64 [%0],%1;" :: "r"(bar), "r"(cnt) : "memory");
}
__device__ __forceinline__ void mbar_expect(uint32_t bar, uint32_t tx) {
    asm volatile("mbarrier.arrive.expect_tx.shared.b64 _,[%0],%1;" :: "r"(bar), "r"(tx) : "memory");
}
__device__ __forceinline__ void mbar_wait_cluster(uint32_t bar, uint32_t parity) {
    uint32_t done;
    do {
        asm volatile("{\n\t.reg .pred p;\n\t"
                     "mbarrier.try_wait.parity.acquire.cluster.shared::cta.b64 p,[%1],%2,0x989680;\n\t"
                     "selp.b32 %0,1,0,p;\n\t}"
                     : "=r"(done) : "r"(bar), "r"(parity) : "memory");
    } while (!done);
}
__device__ __forceinline__ void st_async_b64(uint32_t raddr, unsigned long long v, uint32_t rbar) {
    asm volatile("st.async.shared::cluster.mbarrier::complete_tx::bytes.b64 [%0],%1,[%2];"
                 :: "r"(raddr), "l"(v), "r"(rbar) : "memory");
}
__device__ __forceinline__ void st_async_b32(uint32_t raddr, uint32_t v, uint32_t rbar) {
    asm volatile("st.async.shared::cluster.mbarrier::complete_tx::bytes.b32 [%0],%1,[%2];"
                 :: "r"(raddr), "r"(v), "r"(rbar) : "memory");
}
__device__ __forceinline__ unsigned long long packf2(float x, float y) {
    unsigned long long v; asm("mov.b64 %0,{%1,%2};" : "=l"(v) : "f"(x), "f"(y));
    return v;
}

#define ASTR 136   // bf16 elems per smem row (128 + 8 pad: conflict-free ldmatrix)

// ================= Kernel 1: input projection via tensor cores ==============
__global__ __launch_bounds__(256) void k_xp2(const int* __restrict__ ids)
{
    extern __shared__ char sm[];
    __nv_bfloat16* As = (__nv_bfloat16*)sm;                      // [128][136]
    __nv_bfloat16* Bs = (__nv_bfloat16*)(sm + 128 * ASTR * 2);   // [128][136]
    float* sbias = (float*)(sm + 2 * 128 * ASTR * 2);            // [128]

    const int t = blockIdx.x;          // M tile == timestep
    const int nt = blockIdx.y;         // 0..7
    const int dir = nt >> 2;
    const int gBase = (nt & 3) * 128;
    const int tid = threadIdx.x;

    {
        int r = tid >> 1, half = tid & 1;
        int id = ids[r * Tn + t];
        const uint4* src = (const uint4*)(g_embed_bf + (size_t)id * En + half * 64);
        uint4* dst = (uint4*)(As + r * ASTR + half * 64);
#pragma unroll
        for (int i = 0; i < 8; i++) dst[i] = src[i];
        const uint4* wsrc = (const uint4*)(g_wih_bf + ((size_t)dir * G4H + gBase + r) * En + half * 64);
        uint4* wdst = (uint4*)(Bs + r * ASTR + half * 64);
#pragma unroll
        for (int i = 0; i < 8; i++) wdst[i] = wsrc[i];
    }
    if (tid < 128) sbias[tid] = g_bias[dir * G4H + gBase + tid];
    __syncthreads();

    const int wid = tid >> 5, lane = tid & 31;
    const int wm = (wid & 3) * 32;
    const int wn = (wid >> 2) * 64;

    float acc[2][8][4];
#pragma unroll
    for (int im = 0; im < 2; im++)
#pragma unroll
        for (int inn = 0; inn < 8; inn++)
#pragma unroll
            for (int r = 0; r < 4; r++) acc[im][inn][r] = 0.0f;

    const int lr = lane & 15, lc = lane >> 4;
#pragma unroll
    for (int kk = 0; kk < 8; kk++) {
        uint32_t a[2][4];
#pragma unroll
        for (int im = 0; im < 2; im++) {
            uint32_t ad = smaddr(As + (wm + im * 16 + lr) * ASTR + kk * 16 + lc * 8);
            ldm4(a[im][0], a[im][1], a[im][2], a[im][3], ad);
        }
        uint32_t b[4][4];
#pragma unroll
        for (int np = 0; np < 4; np++) {
            uint32_t ad = smaddr(Bs + (wn + np * 16 + lr) * ASTR + kk * 16 + lc * 8);
            ldm4(b[np][0], b[np][1], b[np][2], b[np][3], ad);
        }
#pragma unroll
        for (int im = 0; im < 2; im++)
#pragma unroll
            for (int inn = 0; inn < 8; inn++) {
                int np = inn >> 1, hf = inn & 1;
                uint32_t bb0 = hf ? b[np][1] : b[np][0];
                uint32_t bb1 = hf ? b[np][3] : b[np][2];
                mma16816(acc[im][inn], a[im][0], a[im][1], a[im][2], a[im][3], bb0, bb1);
            }
    }

    const int trow = dir ? (Tn - 1 - t) : t;
    float* outBase = g_xp + (((size_t)dir * Tn + trow) * Bn) * G4H;
#pragma unroll
    for (int im = 0; im < 2; im++)
#pragma unroll
        for (int inn = 0; inn < 8; inn++) {
            int gl = wn + inn * 8 + 2 * (lane & 3);
            float bx = sbias[gl], by = sbias[gl + 1];
            int row0 = wm + im * 16 + (lane >> 2);
            float2 v0 = {acc[im][inn][0] + bx, acc[im][inn][1] + by};
            float2 v1 = {acc[im][inn][2] + bx, acc[im][inn][3] + by};
            *(float2*)(outBase + (size_t)row0 * G4H + gBase + gl) = v0;
            *(float2*)(outBase + (size_t)(row0 + 8) * G4H + gBase + gl) = v1;
        }
}

// ================= Kernel 2: cluster-4 gate-split BiLSTM recurrence =========
// Cluster of 4 CTAs = one (dir, 16-batch group). CTA rank q computes gate q
// (N=128 cols, M=16 real batch rows). W fragments hoisted to registers.
// Gates scattered to the batch-owning CTA via st.async + mbarrier tx; h
// broadcast back the same way. 16 clusters x 4 = 64 CTAs.
#define GSTRIDE 516

__global__ __launch_bounds__(256, 1) __cluster_dims__(4, 1, 1)
void k_lstm4(const float* __restrict__ whhf, const float* __restrict__ whhb)
{
    __shared__ __nv_bfloat16 Wsm[128 * ASTR];   // my gate's W rows (bf16)
    __shared__ __nv_bfloat16 Hsm[16 * ASTR];    // current h, 16 batches (bf16)
    __shared__ float Gs[4 * GSTRIDE];           // gates for MY 4 batches [b][512]
    __shared__ __align__(8) unsigned long long bars[2];   // [0]=gates, [1]=h

    const int cid = blockIdx.x >> 2;
    const int rank = blockIdx.x & 3;
    const int dir = cid >> 3;
    const int b0 = (cid & 7) * 16;
    const float* whh = dir ? whhb : whhf;
    const int tid = threadIdx.x;
    const int wid = tid >> 5, lane = tid & 31;

    // ---- load my 128 W_hh rows (gate block `rank`) as bf16 ----
    {
        int row = tid >> 1, half = tid & 1;
        const float2* src = (const float2*)(whh + (size_t)(128 * rank + row) * Hn + half * 64);
        __nv_bfloat162* dst = (__nv_bfloat162*)(Wsm + row * ASTR + half * 64);
#pragma unroll
        for (int i = 0; i < 32; i++) {
            float2 v = src[i];
            dst[i] = __floats2bfloat162_rn(v.x, v.y);
        }
    }
    for (int i = tid; i < 16 * ASTR / 2; i += 256) ((uint32_t*)Hsm)[i] = 0u;

    const uint32_t gbar = smaddr(&bars[0]);
    const uint32_t hbar = smaddr(&bars[1]);
    if (tid == 0) {
        mbar_init(gbar, 1);
        mbar_init(hbar, 1);
        mbar_expect(gbar, 8192);   // phase 0: 4 srcs x 4 rows x 128 x 4B
        mbar_expect(hbar, 4096);   // phase 0: 16 rows x 128 x 2B
    }
    __syncthreads();
    asm volatile("barrier.cluster.arrive.aligned;" ::: "memory");
    asm volatile("barrier.cluster.wait.aligned;" ::: "memory");

    // ---- hoist W fragments into registers (step-invariant) ----
    const int lr = lane & 15, lc = lane >> 4;
    uint32_t bw[8][4];
#pragma unroll
    for (int kk = 0; kk < 8; kk++)
        ldm4(bw[kk][0], bw[kk][1], bw[kk][2], bw[kk][3],
             smaddr(Wsm + (wid * 16 + lr) * ASTR + kk * 16 + lc * 8));

    // ---- precompute scatter addresses ----
    const int row0 = lane >> 2;                 // batches row0 and row0+8
    const int colb = 16 * wid + 2 * (lane & 3); // col within my 128-slice
    const int pLo = row0 >> 2, pHi = pLo + 2;
    const int idx = row0 & 3;                   // Gs row at target
    uint32_t aGlo[2], aGhi[2];
#pragma unroll
    for (int np = 0; np < 2; np++) {
        uint32_t la = smaddr(&Gs[idx * GSTRIDE + 128 * rank + colb + 8 * np]);
        aGlo[np] = mapa_u32(la, pLo);
        aGhi[np] = mapa_u32(la, pHi);
    }
    const uint32_t barGlo = mapa_u32(gbar, pLo);
    const uint32_t barGhi = mapa_u32(gbar, pHi);

    const int b_local = tid >> 6;               // epilogue batch (of my 4)
    const int jj = (tid & 63) * 2;              // epilogue j pair
    const int bglob = 4 * rank + b_local;       // group-batch index 0..15
    uint32_t aH[4], barH[4];
    {
        uint32_t la = smaddr(Hsm + bglob * ASTR + jj);
#pragma unroll
        for (int p = 0; p < 4; p++) {
            aH[p] = mapa_u32(la, p);
            barH[p] = mapa_u32(hbar, p);
        }
    }

    // ---- xp streaming pointers ----
    const float* xpLo = g_xp + (size_t)dir * Tn * Bn * G4H
                       + (size_t)(b0 + row0) * G4H + 128 * rank + colb;
    const float* xpHi = xpLo + (size_t)8 * G4H;
    const size_t tstride = (size_t)Bn * G4H;

    float2 xpc[4], xpn[4];
    xpc[0] = *(const float2*)(xpLo);
    xpc[1] = *(const float2*)(xpLo + 8);
    xpc[2] = *(const float2*)(xpHi);
    xpc[3] = *(const float2*)(xpHi + 8);

    float2 creg = {0.0f, 0.0f};

    for (int t = 0; t < Tn; t++) {
        if (t + 1 < Tn) {
            const float* pl = xpLo + (size_t)(t + 1) * tstride;
            const float* ph = xpHi + (size_t)(t + 1) * tstride;
            xpn[0] = *(const float2*)(pl);
            xpn[1] = *(const float2*)(pl + 8);
            xpn[2] = *(const float2*)(ph);
            xpn[3] = *(const float2*)(ph + 8);
        }
        // ---- GEMM: gates = xp + h @ W^T  (M16 x N128 x K128 per CTA) ----
        float acc[2][4];
#pragma unroll
        for (int np = 0; np < 2; np++) {
            acc[np][0] = xpc[np].x;
            acc[np][1] = xpc[np].y;
            acc[np][2] = xpc[2 + np].x;
            acc[np][3] = xpc[2 + np].y;
        }
#pragma unroll
        for (int kk = 0; kk < 8; kk++) {
            uint32_t a0, a1, a2, a3;
            ldm4(a0, a1, a2, a3, smaddr(Hsm + lr * ASTR + kk * 16 + lc * 8));
            mma16816(acc[0], a0, a1, a2, a3, bw[kk][0], bw[kk][2]);
            mma16816(acc[1], a0, a1, a2, a3, bw[kk][1], bw[kk][3]);
        }
        // ---- scatter gate fragments to batch owners ----
#pragma unroll
        for (int np = 0; np < 2; np++) {
            st_async_b64(aGlo[np], packf2(acc[np][0], acc[np][1]), barGlo);
            st_async_b64(aGhi[np], packf2(acc[np][2], acc[np][3]), barGhi);
        }
        mbar_wait_cluster(gbar, t & 1);
        if (tid == 0) mbar_expect(gbar, 8192);

        // ---- pointwise epilogue for my 4 batches (2 j per thread) ----
        {
            const float* gb = &Gs[b_local * GSTRIDE];
            float2 gi = *(const float2*)&gb[jj];
            float2 gf = *(const float2*)&gb[128 + jj];
            float2 gg = *(const float2*)&gb[256 + jj];
            float2 go = *(const float2*)&gb[384 + jj];
            creg.x = siga(gf.x) * creg.x + siga(gi.x) * tanha(gg.x);
            creg.y = siga(gf.y) * creg.y + siga(gi.y) * tanha(gg.y);
            float h0 = siga(go.x) * tanha(creg.x);
            float h1 = siga(go.y) * tanha(creg.y);

            __nv_bfloat162 hp = __floats2bfloat162_rn(h0, h1);
            uint32_t hv = *(uint32_t*)&hp;
            if (t + 1 < Tn) {
#pragma unroll
                for (int p = 0; p < 4; p++) st_async_b32(aH[p], hv, barH[p]);
            }
            int trow = dir ? (Tn - 1 - t) : t;
            float2 hg = {h0, h1};
            *(float2*)(g_hs + ((size_t)trow * Bn + (b0 + bglob)) * (2 * Hn) + dir * Hn + jj) = hg;
        }
        if (t + 1 < Tn) {
            mbar_wait_cluster(hbar, t & 1);
            if (tid == 0) mbar_expect(hbar, 4096);
        }
#pragma unroll
        for (int q = 0; q < 4; q++) xpc[q] = xpn[q];
    }
}

// ================= Kernel 3: emissions ======================================
__global__ __launch_bounds__(544) void k_emit(
    const float* __restrict__ w_emit, const float* __restrict__ b_emit)
{
    __shared__ float ws[Kn * 257];
    const int tid = threadIdx.x;
    for (int i = tid; i < Kn * 256; i += 544)
        ws[(i >> 8) * 257 + (i & 255)] = w_emit[i];
    __syncthreads();

    const int kk = tid % 17;
    const int blc = tid / 17;
    const int bt = blockIdx.x * 32 + blc;   // bt = t*B + b
    const int t = bt >> 7, b = bt & 127;

    const float4* hv = (const float4*)(g_hs + (size_t)bt * 256);
    const float* wr = &ws[kk * 257];
    float dot = 0.0f;
#pragma unroll 8
    for (int i = 0; i < 64; i++) {
        float4 h4 = hv[i];
        dot += h4.x * wr[i * 4 + 0] + h4.y * wr[i * 4 + 1]
             + h4.z * wr[i * 4 + 2] + h4.w * wr[i * 4 + 3];
    }
    g_em[((size_t)b * Tn + t) * Kn + kk] = dot + b_emit[kk];
}

// ================= Kernel 4: CRF, two interleaved batches per warp ==========
__global__ void k_crf(const int* __restrict__ tags,
                      const float* __restrict__ start_t,
                      const float* __restrict__ end_t,
                      const float* __restrict__ trans)
{
    const int lane = threadIdx.x;
    const int bA = blockIdx.x, bB = blockIdx.x + 64;
    const float* emA = g_em + (size_t)bA * Tn * Kn;
    const float* emB = g_em + (size_t)bB * Tn * Kn;

    float tcol[Kn];
#pragma unroll
    for (int i = 0; i < Kn; i++)
        tcol[i] = (lane < Kn) ? trans[i * Kn + lane] : 0.0f;

    float alA = (lane < Kn) ? (start_t[lane] + emA[lane]) : -1e30f;
    float alB = (lane < Kn) ? (start_t[lane] + emB[lane]) : -1e30f;

    int tpA = tags[bA * Tn], tpB = tags[bB * Tn];
    float scA = start_t[tpA] + emA[tpA];
    float scB = start_t[tpB] + emB[tpB];

    const int laneC = (lane < Kn) ? lane : 0;
    float ecA = emA[Kn + laneC], ecB = emB[Kn + laneC];
    int tcA = tags[bA * Tn + 1], tcB = tags[bB * Tn + 1];

    for (int t = 1; t < Tn; t++) {
        float enA = 0.0f, enB = 0.0f;
        int tnA = 0, tnB = 0;
        if (t + 1 < Tn) {
            enA = emA[(size_t)(t + 1) * Kn + laneC];
            tnA = tags[bA * Tn + t + 1];
            enB = emB[(size_t)(t + 1) * Kn + laneC];
            tnB = tags[bB * Tn + t + 1];
        }
        float vA[Kn], vB[Kn];
        float mA = -1e30f, mB = -1e30f;
#pragma unroll
        for (int i = 0; i < Kn; i++) {
            float aiA = __shfl_sync(0xffffffffu, alA, i);
            float aiB = __shfl_sync(0xffffffffu, alB, i);
            vA[i] = aiA + tcol[i];
            vB[i] = aiB + tcol[i];
            mA = fmaxf(mA, vA[i]);
            mB = fmaxf(mB, vB[i]);
        }
        float sA = 0.0f, sB = 0.0f;
#pragma unroll
        for (int i = 0; i < Kn; i++) {
            sA += __expf(vA[i] - mA);
            sB += __expf(vB[i] - mB);
        }
        float naA = mA + __logf(sA) + ecA;
        float naB = mB + __logf(sB) + ecB;
        if (lane < Kn) { alA = naA; alB = naB; }

        scA += trans[tpA * Kn + tcA] + emA[(size_t)t * Kn + tcA];
        scB += trans[tpB * Kn + tcB] + emB[(size_t)t * Kn + tcB];
        tpA = tcA; tpB = tcB;
        ecA = enA; ecB = enB; tcA = tnA; tcB = tnB;
    }
    scA += end_t[tpA];
    scB += end_t[tpB];

    float xA = (lane < Kn) ? (alA + end_t[lane]) : -1e30f;
    float xB = (lane < Kn) ? (alB + end_t[lane]) : -1e30f;
    float mA = xA, mB = xB;
#pragma unroll
    for (int off = 16; off; off >>= 1) {
        mA = fmaxf(mA, __shfl_xor_sync(0xffffffffu, mA, off));
        mB = fmaxf(mB, __shfl_xor_sync(0xffffffffu, mB, off));
    }
    float sA = __expf(xA - mA), sB = __expf(xB - mB);
#pragma unroll
    for (int off = 16; off; off >>= 1) {
        sA += __shfl_xor_sync(0xffffffffu, sA, off);
        sB += __shfl_xor_sync(0xffffffffu, sB, off);
    }
    if (lane == 0) {
        g_llh[bA] = scA - (mA + __logf(sA));
        g_llh[bB] = scB - (mB + __logf(sB));
    }
}

// ================= Kernel 5: final mean =====================================
__global__ void k_reduce(float* __restrict__ out)
{
    const int tid = threadIdx.x; // 128
    float v = g_llh[tid];
#pragma unroll
    for (int off = 16; off; off >>= 1) v += __shfl_xor_sync(0xffffffffu, v, off);
    __shared__ float s[4];
    if ((tid & 31) == 0) s[tid >> 5] = v;
    __syncthreads();
    if (tid == 0) out[0] = -(s[0] + s[1] + s[2] + s[3]) / (float)Bn;
}

// ============================================================================
extern "C" void kernel_launch(void* const* d_in, const int* in_sizes, int n_in,
                              void* d_out, int out_size)
{
    const int*   ids     = (const int*)d_in[0];
    const int*   tags    = (const int*)d_in[1];
    // d_in[2] = mask: all-true for this problem; intentionally unused.
    const float* embed   = (const float*)d_in[3];
    const float* w_ih_f  = (const float*)d_in[4];
    const float* w_hh_f  = (const float*)d_in[5];
    const float* b_ih_f  = (const float*)d_in[6];
    const float* b_hh_f  = (const float*)d_in[7];
    const float* w_ih_b  = (const float*)d_in[8];
    const float* w_hh_b  = (const float*)d_in[9];
    const float* b_ih_b  = (const float*)d_in[10];
    const float* b_hh_b  = (const float*)d_in[11];
    const float* w_emit  = (const float*)d_in[12];
    const float* b_emit  = (const float*)d_in[13];
    const float* start_t = (const float*)d_in[14];
    const float* end_t   = (const float*)d_in[15];
    const float* trans   = (const float*)d_in[16];

    const int SMEM_XP2 = 2 * 128 * ASTR * 2 + 512;   // 70,144 B
    cudaFuncSetAttribute(k_xp2, cudaFuncAttributeMaxDynamicSharedMemorySize, SMEM_XP2);

    k_cvt<<<Vn * En / 2 / 256, 256>>>(embed, w_ih_f, w_ih_b,
                                      b_ih_f, b_hh_f, b_ih_b, b_hh_b);
    k_xp2<<<dim3(512, 8), 256, SMEM_XP2>>>(ids);
    k_lstm4<<<64, 256>>>(w_hh_f, w_hh_b);
    k_emit<<<2048, 544>>>(w_emit, b_emit);
    k_crf<<<64, 32>>>(tags, start_t, end_t, trans);
    k_reduce<<<1, 128>>>((float*)d_out);
}

// round 8
// speedup vs baseline: 2.4783x; 1.1005x over previous
#include <cuda_runtime.h>
#include <cuda_bf16.h>
#include <cstdint>

#define Vn 30000
#define Kn 17
#define En 128
#define Hn 128
#define Bn 128
#define Tn 512
#define G4H 512   // 4*H

// ---------------- scratch (device globals; allocation-free) ----------------
// xp stored bf16, layout [dir][t][rank][b][128] with gate-permuted last dim:
//   c = (wid'<<4) | ((gate&2)<<2) | (a<<1) | (gate&1),  j = 32*rank + 4*wid' + a
__device__ __nv_bfloat16 g_xp_bf[(size_t)2 * Tn * 4 * Bn * 128];
__device__ __nv_bfloat16 g_hs_bf[(size_t)Tn * Bn * 2 * Hn];   // [t*B+b][256]
__device__ float g_em[(size_t)Bn * Tn * Kn];                  // [b][t][k]
__device__ float g_llh[Bn];
__device__ __nv_bfloat16 g_embed_bf[(size_t)Vn * En];
__device__ __nv_bfloat16 g_wih_bf[2 * (size_t)G4H * En];      // [dir][g][k]
__device__ __nv_bfloat16 g_wemit_bf[32 * 256];                // rows>=17 zero
__device__ float g_bias[2 * G4H];

__device__ __forceinline__ float tanha(float x) {
    float r; asm("tanh.approx.f32 %0,%1;" : "=f"(r) : "f"(x)); return r;
}
__device__ __forceinline__ float siga(float x) {
    return 0.5f * tanha(0.5f * x) + 0.5f;
}

// ================= Kernel 0: fp32 -> bf16 conversions =======================
__global__ __launch_bounds__(256) void k_cvt(
    const float* __restrict__ embed,
    const float* __restrict__ wf, const float* __restrict__ wb,
    const float* __restrict__ bihf, const float* __restrict__ bhhf,
    const float* __restrict__ bihb, const float* __restrict__ bhhb,
    const float* __restrict__ w_emit)
{
    int i = blockIdx.x * 256 + threadIdx.x;
    if (i < Vn * En / 2) {
        float2 v = ((const float2*)embed)[i];
        ((__nv_bfloat162*)g_embed_bf)[i] = __floats2bfloat162_rn(v.x, v.y);
    }
    if (i < G4H * En / 2) {
        float2 v = ((const float2*)wf)[i];
        ((__nv_bfloat162*)g_wih_bf)[i] = __floats2bfloat162_rn(v.x, v.y);
        float2 u = ((const float2*)wb)[i];
        ((__nv_bfloat162*)g_wih_bf)[G4H * En / 2 + i] = __floats2bfloat162_rn(u.x, u.y);
    }
    if (i < G4H) {
        g_bias[i] = bihf[i] + bhhf[i];
        g_bias[G4H + i] = bihb[i] + bhhb[i];
    }
    if (i < 32 * 128) {   // w_emit padded to 32 rows, bf16
        int row = i >> 7, col2 = i & 127;
        __nv_bfloat162 v;
        if (row < Kn) {
            v = __floats2bfloat162_rn(w_emit[row * 256 + 2 * col2],
                                      w_emit[row * 256 + 2 * col2 + 1]);
        } else {
            v = __floats2bfloat162_rn(0.0f, 0.0f);
        }
        ((__nv_bfloat162*)g_wemit_bf)[i] = v;
    }
}

// ---------------- mma / cluster helpers ----------------
__device__ __forceinline__ uint32_t smaddr(const void* p) {
    return (uint32_t)__cvta_generic_to_shared(p);
}
__device__ __forceinline__ void ldm4(uint32_t& r0, uint32_t& r1, uint32_t& r2, uint32_t& r3, uint32_t a) {
    asm volatile("ldmatrix.sync.aligned.m8n8.x4.shared.b16 {%0,%1,%2,%3},[%4];"
                 : "=r"(r0), "=r"(r1), "=r"(r2), "=r"(r3) : "r"(a));
}
__device__ __forceinline__ void mma16816(float* c, uint32_t a0, uint32_t a1, uint32_t a2, uint32_t a3,
                                         uint32_t b0, uint32_t b1) {
    asm volatile("mma.sync.aligned.m16n8k16.row.col.f32.bf16.bf16.f32 "
                 "{%0,%1,%2,%3},{%4,%5,%6,%7},{%8,%9},{%0,%1,%2,%3};"
                 : "+f"(c[0]), "+f"(c[1]), "+f"(c[2]), "+f"(c[3])
                 : "r"(a0), "r"(a1), "r"(a2), "r"(a3), "r"(b0), "r"(b1));
}
__device__ __forceinline__ uint32_t mapa_u32(uint32_t a, uint32_t rnk) {
    uint32_t d; asm("mapa.shared::cluster.u32 %0,%1,%2;" : "=r"(d) : "r"(a), "r"(rnk));
    return d;
}
__device__ __forceinline__ void mbar_init(uint32_t bar, uint32_t cnt) {
    asm volatile("mbarrier.init.shared.b64 [%0],%1;" :: "r"(bar), "r"(cnt) : "memory");
}
__device__ __forceinline__ void mbar_expect(uint32_t bar, uint32_t tx) {
    asm volatile("mbarrier.arrive.expect_tx.shared.b64 _,[%0],%1;" :: "r"(bar), "r"(tx) : "memory");
}
__device__ __forceinline__ void mbar_wait_cluster(uint32_t bar, uint32_t parity) {
    uint32_t done;
    do {
        asm volatile("{\n\t.reg .pred p;\n\t"
                     "mbarrier.try_wait.parity.acquire.cluster.shared::cta.b64 p,[%1],%2,0x989680;\n\t"
                     "selp.b32 %0,1,0,p;\n\t}"
                     : "=r"(done) : "r"(bar), "r"(parity) : "memory");
    } while (!done);
}
__device__ __forceinline__ void st_async_b32(uint32_t raddr, uint32_t v, uint32_t rbar) {
    asm volatile("st.async.shared::cluster.mbarrier::complete_tx::bytes.b32 [%0],%1,[%2];"
                 :: "r"(raddr), "r"(v), "r"(rbar) : "memory");
}

#define ASTR 136   // bf16 elems per smem row (128 + 8 pad: conflict-free ldmatrix)

// ================= Kernel 1: input projection (tensor cores, permuted out) ==
// grid (8, 512): x = nt (dir*4+gate), y = t.
__global__ __launch_bounds__(256) void k_xp2(const int* __restrict__ ids)
{
    extern __shared__ char sm[];
    __nv_bfloat16* As = (__nv_bfloat16*)sm;                      // [128][136]
    __nv_bfloat16* Bs = (__nv_bfloat16*)(sm + 128 * ASTR * 2);   // [128][136]
    float* sbias = (float*)(sm + 2 * 128 * ASTR * 2);            // [128]

    const int t = blockIdx.y;
    const int nt = blockIdx.x;         // 0..7
    const int dir = nt >> 2;
    const int gate = nt & 3;
    const int gBase = gate * 128;
    const int tid = threadIdx.x;

    {
        int r = tid >> 1, half = tid & 1;
        int id = ids[r * Tn + t];
        const uint4* src = (const uint4*)(g_embed_bf + (size_t)id * En + half * 64);
        uint4* dst = (uint4*)(As + r * ASTR + half * 64);
#pragma unroll
        for (int i = 0; i < 8; i++) dst[i] = src[i];
        const uint4* wsrc = (const uint4*)(g_wih_bf + ((size_t)dir * G4H + gBase + r) * En + half * 64);
        uint4* wdst = (uint4*)(Bs + r * ASTR + half * 64);
#pragma unroll
        for (int i = 0; i < 8; i++) wdst[i] = wsrc[i];
    }
    if (tid < 128) sbias[tid] = g_bias[dir * G4H + gBase + tid];
    __syncthreads();

    const int wid = tid >> 5, lane = tid & 31;
    const int wm = (wid & 3) * 32;
    const int wn = (wid >> 2) * 64;

    float acc[2][8][4];
#pragma unroll
    for (int im = 0; im < 2; im++)
#pragma unroll
        for (int inn = 0; inn < 8; inn++)
#pragma unroll
            for (int r = 0; r < 4; r++) acc[im][inn][r] = 0.0f;

    const int lr = lane & 15, lc = lane >> 4;
#pragma unroll
    for (int kk = 0; kk < 8; kk++) {
        uint32_t a[2][4];
#pragma unroll
        for (int im = 0; im < 2; im++) {
            uint32_t ad = smaddr(As + (wm + im * 16 + lr) * ASTR + kk * 16 + lc * 8);
            ldm4(a[im][0], a[im][1], a[im][2], a[im][3], ad);
        }
        uint32_t b[4][4];
#pragma unroll
        for (int np = 0; np < 4; np++) {
            uint32_t ad = smaddr(Bs + (wn + np * 16 + lr) * ASTR + kk * 16 + lc * 8);
            ldm4(b[np][0], b[np][1], b[np][2], b[np][3], ad);
        }
#pragma unroll
        for (int im = 0; im < 2; im++)
#pragma unroll
            for (int inn = 0; inn < 8; inn++) {
                int np = inn >> 1, hf = inn & 1;
                uint32_t bb0 = hf ? b[np][1] : b[np][0];
                uint32_t bb1 = hf ? b[np][3] : b[np][2];
                mma16816(acc[im][inn], a[im][0], a[im][1], a[im][2], a[im][3], bb0, bb1);
            }
    }

    // epilogue: bias, bf16, permuted scatter to [dir][trow][rank][b][c]
    const int trow = dir ? (Tn - 1 - t) : t;
#pragma unroll
    for (int im = 0; im < 2; im++)
#pragma unroll
        for (int inn = 0; inn < 8; inn++) {
            int gl = wn + inn * 8 + 2 * (lane & 3);       // j (even)
            float bx = sbias[gl], by = sbias[gl + 1];
            int rho = gl >> 5, jl = gl & 31;
            int widp = jl >> 2, aa = jl & 3;
            int cpos = (widp << 4) | ((gate & 2) << 2) | (aa << 1) | (gate & 1);
            int row0 = wm + im * 16 + (lane >> 2);
            size_t base = (((size_t)(dir * Tn + trow) * 4 + rho) * Bn) * 128;
            g_xp_bf[base + (size_t)row0 * 128 + cpos]     = __float2bfloat16(acc[im][inn][0] + bx);
            g_xp_bf[base + (size_t)row0 * 128 + cpos + 2] = __float2bfloat16(acc[im][inn][1] + by);
            g_xp_bf[base + (size_t)(row0 + 8) * 128 + cpos]     = __float2bfloat16(acc[im][inn][2] + bx);
            g_xp_bf[base + (size_t)(row0 + 8) * 128 + cpos + 2] = __float2bfloat16(acc[im][inn][3] + by);
        }
}

// ================= Kernel 2: cluster-4 j-split BiLSTM recurrence ============
// Cluster of 4 CTAs = one (dir, 16-batch group). CTA rank owns j-range
// [32*rank, 32*rank+32): all 4 gates (W rows permuted so each MMA fragment
// holds i,f,g,o of one (b,j) in-thread). Pointwise fully in registers; only
// h is exchanged (st.async). TWO alternating mbarriers (step t uses
// bars[t&1], parity (t>>1)&1) so tx bytes can never be misattributed across
// phases (sound: reuse of a barrier requires a full round on the other).
__global__ __launch_bounds__(256, 1) __cluster_dims__(4, 1, 1)
void k_lstm5(const float* __restrict__ whhf, const float* __restrict__ whhb)
{
    __shared__ __nv_bfloat16 Wsm[128 * ASTR];
    __shared__ __nv_bfloat16 Hsm[2][16 * ASTR];
    __shared__ __align__(8) unsigned long long hbar_s[2];

    const int cid = blockIdx.x >> 2;
    const int rank = blockIdx.x & 3;
    const int dir = cid >> 3;
    const int b0 = (cid & 7) * 16;
    const float* whh = dir ? whhb : whhf;
    const int tid = threadIdx.x;
    const int wid = tid >> 5, lane = tid & 31;

    // ---- load my 128 permuted W_hh rows as bf16 ----
    {
        int c = tid >> 1, half = tid & 1;
        int gate = (c & 1) + 2 * ((c >> 3) & 1);
        int jl = 4 * (c >> 4) + ((c & 7) >> 1);
        int grow = gate * 128 + 32 * rank + jl;
        const float2* src = (const float2*)(whh + (size_t)grow * Hn + half * 64);
        __nv_bfloat162* dst = (__nv_bfloat162*)(Wsm + c * ASTR + half * 64);
#pragma unroll
        for (int i = 0; i < 32; i++) {
            float2 v = src[i];
            dst[i] = __floats2bfloat162_rn(v.x, v.y);
        }
    }
    for (int i = tid; i < 2 * 16 * ASTR / 2; i += 256) ((uint32_t*)Hsm)[i] = 0u;

    const uint32_t hbar0 = smaddr(&hbar_s[0]);
    const uint32_t hbar1 = smaddr(&hbar_s[1]);
    if (tid == 0) {
        mbar_init(hbar0, 1);
        mbar_init(hbar1, 1);
        mbar_expect(hbar0, 4096);   // phase 0 of barrier 0
        mbar_expect(hbar1, 4096);   // phase 0 of barrier 1
    }
    __syncthreads();
    asm volatile("barrier.cluster.arrive.aligned;" ::: "memory");
    asm volatile("barrier.cluster.wait.aligned;" ::: "memory");

    // ---- hoist W fragments (step-invariant) ----
    const int lr = lane & 15, lc = lane >> 4;
    uint32_t bw[8][4];
#pragma unroll
    for (int kk = 0; kk < 8; kk++)
        ldm4(bw[kk][0], bw[kk][1], bw[kk][2], bw[kk][3],
             smaddr(Wsm + (16 * wid + lr) * ASTR + kk * 16 + lc * 8));

    // ---- thread coords & precomputed addresses ----
    const int a = lane & 3, r = lane >> 2;
    const int cb = 16 * wid + 2 * a;
    const int j = 32 * rank + 4 * wid + a;
    const int destrow = (a & 1) ? (r + 8) : r;
    const int destcol = (a & 1) ? (j - 1) : j;   // even
    uint32_t aH[2][4], barH[2][4];
#pragma unroll
    for (int buf = 0; buf < 2; buf++) {
        uint32_t la = smaddr(&Hsm[buf][destrow * ASTR + destcol]);
#pragma unroll
        for (int p = 0; p < 4; p++) aH[buf][p] = mapa_u32(la, p);
    }
#pragma unroll
    for (int p = 0; p < 4; p++) {
        barH[0][p] = mapa_u32(hbar0, p);
        barH[1][p] = mapa_u32(hbar1, p);
    }

    const uint32_t* xb = (const uint32_t*)g_xp_bf
        + ((size_t)dir * Tn * 4 + rank) * Bn * 64 + (size_t)(b0 + r) * 64 + (cb >> 1);
    const size_t tstep = 4 * (size_t)Bn * 64;   // u32 per t

    const uint32_t ghs_ofs = (uint32_t)(((b0 + destrow) * 256 + dir * 128 + destcol) >> 1);
    uint32_t* ghs = (uint32_t*)g_hs_bf;

    uint32_t v00 = xb[0], v01 = xb[4], v10 = xb[512], v11 = xb[516];
    float creg0 = 0.0f, creg1 = 0.0f;

    for (int t = 0; t < Tn; t++) {
        uint32_t n00, n01, n10, n11;
        if (t + 1 < Tn) {
            const uint32_t* p = xb + (size_t)(t + 1) * tstep;
            n00 = p[0]; n01 = p[4]; n10 = p[512]; n11 = p[516];
        }
        // acc init from permuted xp: acc0={i,f}(r),(r+8); acc1={g,o}(r),(r+8)
        float acc0[4], acc1[4];
        {
            __nv_bfloat162 u;
            u = *(__nv_bfloat162*)&v00; acc0[0] = __bfloat162float(u.x); acc0[1] = __bfloat162float(u.y);
            u = *(__nv_bfloat162*)&v10; acc0[2] = __bfloat162float(u.x); acc0[3] = __bfloat162float(u.y);
            u = *(__nv_bfloat162*)&v01; acc1[0] = __bfloat162float(u.x); acc1[1] = __bfloat162float(u.y);
            u = *(__nv_bfloat162*)&v11; acc1[2] = __bfloat162float(u.x); acc1[3] = __bfloat162float(u.y);
        }
        // GEMM from current h buffer
        const __nv_bfloat16* hb = Hsm[t & 1];
#pragma unroll
        for (int kk = 0; kk < 8; kk++) {
            uint32_t a0, a1, a2, a3;
            ldm4(a0, a1, a2, a3, smaddr(hb + lr * ASTR + kk * 16 + lc * 8));
            mma16816(acc0, a0, a1, a2, a3, bw[kk][0], bw[kk][2]);
            mma16816(acc1, a0, a1, a2, a3, bw[kk][1], bw[kk][3]);
        }
        // pointwise in registers: (i,f,g,o) at (b=r / r+8, j)
        creg0 = siga(acc0[1]) * creg0 + siga(acc0[0]) * tanha(acc1[0]);
        float h0 = siga(acc1[1]) * tanha(creg0);
        creg1 = siga(acc0[3]) * creg1 + siga(acc0[2]) * tanha(acc1[2]);
        float h1 = siga(acc1[3]) * tanha(creg1);

        float h0p = __shfl_xor_sync(0xffffffffu, h0, 1);
        float h1p = __shfl_xor_sync(0xffffffffu, h1, 1);
        __nv_bfloat162 pk = (a & 1) ? __floats2bfloat162_rn(h1p, h1)
                                    : __floats2bfloat162_rn(h0, h0p);
        uint32_t val = *(uint32_t*)&pk;

        int trow = dir ? (Tn - 1 - t) : t;
        ghs[(uint32_t)trow * 16384 + ghs_ofs] = val;

        if (t + 1 < Tn) {
            const int bb = t & 1;               // barrier for this step
            const int nb = (t + 1) & 1;         // h buffer for next step
#pragma unroll
            for (int p = 0; p < 4; p++) st_async_b32(aH[nb][p], val, barH[bb][p]);
            mbar_wait_cluster(bb ? hbar1 : hbar0, (t >> 1) & 1);
            if (tid == 0) mbar_expect(bb ? hbar1 : hbar0, 4096);
            v00 = n00; v01 = n01; v10 = n10; v11 = n11;
        }
    }
}

// ================= Kernel 3: emissions via tensor cores =====================
// em[b][t][k] = h_bf[bt] . w_emit_bf[k] + b_emit[k];  block = 64 bt rows.
#define ESTR 264
__global__ __launch_bounds__(128) void k_emit2(const float* __restrict__ b_emit)
{
    extern __shared__ char sm[];
    __nv_bfloat16* As = (__nv_bfloat16*)sm;                     // [64][264]
    __nv_bfloat16* Bs = (__nv_bfloat16*)(sm + 64 * ESTR * 2);   // [32][264]
    float* sbias = (float*)(sm + (64 + 32) * ESTR * 2);         // [32]

    const int tid = threadIdx.x;
    const int bt0 = blockIdx.x * 64;

    {
        int row = tid >> 1, half = tid & 1;
        const uint4* src = (const uint4*)(g_hs_bf + (size_t)(bt0 + row) * 256 + half * 128);
        uint4* dst = (uint4*)(As + row * ESTR + half * 128);
#pragma unroll
        for (int i = 0; i < 16; i++) dst[i] = src[i];
        if (tid < 64) {
            const uint4* ws = (const uint4*)(g_wemit_bf + (size_t)row * 256 + half * 128);
            uint4* wd = (uint4*)(Bs + row * ESTR + half * 128);
#pragma unroll
            for (int i = 0; i < 16; i++) wd[i] = ws[i];
        }
    }
    if (tid < 32) sbias[tid] = (tid < Kn) ? b_emit[tid] : 0.0f;
    __syncthreads();

    const int wid = tid >> 5, lane = tid & 31;
    const int lr = lane & 15, lc = lane >> 4;

    float acc[3][4];
#pragma unroll
    for (int nt = 0; nt < 3; nt++)
#pragma unroll
        for (int q = 0; q < 4; q++) acc[nt][q] = 0.0f;

#pragma unroll
    for (int kk = 0; kk < 16; kk++) {
        uint32_t a0, a1, a2, a3;
        ldm4(a0, a1, a2, a3, smaddr(As + (16 * wid + lr) * ESTR + kk * 16 + lc * 8));
        uint32_t b0[4], b1[4];
        ldm4(b0[0], b0[1], b0[2], b0[3], smaddr(Bs + lr * ESTR + kk * 16 + lc * 8));
        ldm4(b1[0], b1[1], b1[2], b1[3], smaddr(Bs + (16 + lr) * ESTR + kk * 16 + lc * 8));
        mma16816(acc[0], a0, a1, a2, a3, b0[0], b0[2]);   // n 0..7
        mma16816(acc[1], a0, a1, a2, a3, b0[1], b0[3]);   // n 8..15
        mma16816(acc[2], a0, a1, a2, a3, b1[0], b1[2]);   // n 16..23
    }

    const int r = lane >> 2;
#pragma unroll
    for (int nt = 0; nt < 3; nt++) {
#pragma unroll
        for (int q = 0; q < 4; q++) {
            int n = 8 * nt + 2 * (lane & 3) + (q & 1);
            if (n >= Kn) continue;
            int bt = bt0 + 16 * wid + r + ((q >> 1) ? 8 : 0);
            int t = bt >> 7, b = bt & 127;
            g_em[((size_t)b * Tn + t) * Kn + n] = acc[nt][q] + sbias[n];
        }
    }
}

// ================= Kernel 4: CRF (linear-domain forward), 4 batches/warp ====
__global__ void k_crf2(const int* __restrict__ tags,
                       const float* __restrict__ start_t,
                       const float* __restrict__ end_t,
                       const float* __restrict__ trans)
{
    const int lane = threadIdx.x;
    const int laneC = (lane < Kn) ? lane : 0;
    int bidx[4];
    const float* em[4];
    const int* tg[4];
#pragma unroll
    for (int q = 0; q < 4; q++) {
        bidx[q] = blockIdx.x + 32 * q;
        em[q] = g_em + (size_t)bidx[q] * Tn * Kn;
        tg[q] = tags + bidx[q] * Tn;
    }

    float T[Kn];
#pragma unroll
    for (int i = 0; i < Kn; i++)
        T[i] = (lane < Kn) ? __expf(trans[i * Kn + lane]) : 0.0f;

    // ---- numerator (gold-path score): parallel over t ----
    float sc[4];
#pragma unroll
    for (int q = 0; q < 4; q++) {
        float s = 0.0f;
        for (int t = lane + 1; t < Tn; t += 32)
            s += trans[tg[q][t - 1] * Kn + tg[q][t]] + em[q][(size_t)t * Kn + tg[q][t]];
#pragma unroll
        for (int off = 16; off; off >>= 1) s += __shfl_xor_sync(0xffffffffu, s, off);
        s += start_t[tg[q][0]] + em[q][tg[q][0]] + end_t[tg[q][Tn - 1]];
        sc[q] = s;
    }

    // ---- denominator: linear-domain forward with periodic renorm ----
    float A[4], la[4], ec[4];
#pragma unroll
    for (int q = 0; q < 4; q++) {
        A[q] = (lane < Kn) ? __expf(start_t[lane] + em[q][lane]) : 0.0f;
        la[q] = 0.0f;
        ec[q] = em[q][Kn + laneC];
    }

    for (int t = 1; t < Tn; t++) {
        float en[4];
        if (t + 1 < Tn) {
#pragma unroll
            for (int q = 0; q < 4; q++) en[q] = em[q][(size_t)(t + 1) * Kn + laneC];
        }
        float s0 = 0.f, s1 = 0.f, s2 = 0.f, s3 = 0.f;
#pragma unroll
        for (int i = 0; i < Kn; i++) {
            float a0 = __shfl_sync(0xffffffffu, A[0], i);
            float a1 = __shfl_sync(0xffffffffu, A[1], i);
            float a2 = __shfl_sync(0xffffffffu, A[2], i);
            float a3 = __shfl_sync(0xffffffffu, A[3], i);
            s0 += a0 * T[i]; s1 += a1 * T[i]; s2 += a2 * T[i]; s3 += a3 * T[i];
        }
        A[0] = s0 * __expf(ec[0]);
        A[1] = s1 * __expf(ec[1]);
        A[2] = s2 * __expf(ec[2]);
        A[3] = s3 * __expf(ec[3]);
        if ((t & 3) == 3) {
#pragma unroll
            for (int q = 0; q < 4; q++) {
                float m = A[q];
#pragma unroll
                for (int off = 16; off; off >>= 1)
                    m = fmaxf(m, __shfl_xor_sync(0xffffffffu, m, off));
                la[q] += __logf(m);
                A[q] = __fdividef(A[q], m);
            }
        }
        if (t + 1 < Tn) {
#pragma unroll
            for (int q = 0; q < 4; q++) ec[q] = en[q];
        }
    }

    float Ee = (lane < Kn) ? __expf(end_t[lane]) : 0.0f;
#pragma unroll
    for (int q = 0; q < 4; q++) {
        float x = A[q] * Ee;
#pragma unroll
        for (int off = 16; off; off >>= 1) x += __shfl_xor_sync(0xffffffffu, x, off);
        float logZ = __logf(x) + la[q];
        if (lane == 0) g_llh[bidx[q]] = sc[q] - logZ;
    }
}

// ================= Kernel 5: final mean =====================================
__global__ void k_reduce(float* __restrict__ out)
{
    const int tid = threadIdx.x; // 128
    float v = g_llh[tid];
#pragma unroll
    for (int off = 16; off; off >>= 1) v += __shfl_xor_sync(0xffffffffu, v, off);
    __shared__ float s[4];
    if ((tid & 31) == 0) s[tid >> 5] = v;
    __syncthreads();
    if (tid == 0) out[0] = -(s[0] + s[1] + s[2] + s[3]) / (float)Bn;
}

// ============================================================================
extern "C" void kernel_launch(void* const* d_in, const int* in_sizes, int n_in,
                              void* d_out, int out_size)
{
    const int*   ids     = (const int*)d_in[0];
    const int*   tags    = (const int*)d_in[1];
    // d_in[2] = mask: all-true for this problem; intentionally unused.
    const float* embed   = (const float*)d_in[3];
    const float* w_ih_f  = (const float*)d_in[4];
    const float* w_hh_f  = (const float*)d_in[5];
    const float* b_ih_f  = (const float*)d_in[6];
    const float* b_hh_f  = (const float*)d_in[7];
    const float* w_ih_b  = (const float*)d_in[8];
    const float* w_hh_b  = (const float*)d_in[9];
    const float* b_ih_b  = (const float*)d_in[10];
    const float* b_hh_b  = (const float*)d_in[11];
    const float* w_emit  = (const float*)d_in[12];
    const float* b_emit  = (const float*)d_in[13];
    const float* start_t = (const float*)d_in[14];
    const float* end_t   = (const float*)d_in[15];
    const float* trans   = (const float*)d_in[16];

    const int SMEM_XP2  = 2 * 128 * ASTR * 2 + 512;          // 70,144 B
    const int SMEM_EMIT = (64 + 32) * ESTR * 2 + 128;        // 50,816 B
    cudaFuncSetAttribute(k_xp2,   cudaFuncAttributeMaxDynamicSharedMemorySize, SMEM_XP2);
    cudaFuncSetAttribute(k_emit2, cudaFuncAttributeMaxDynamicSharedMemorySize, SMEM_EMIT);

    k_cvt<<<Vn * En / 2 / 256, 256>>>(embed, w_ih_f, w_ih_b,
                                      b_ih_f, b_hh_f, b_ih_b, b_hh_b, w_emit);
    k_xp2<<<dim3(8, 512), 256, SMEM_XP2>>>(ids);
    k_lstm5<<<64, 256>>>(w_hh_f, w_hh_b);
    k_emit2<<<1024, 128, SMEM_EMIT>>>(b_emit);
    k_crf2<<<32, 32>>>(tags, start_t, end_t, trans);
    k_reduce<<<1, 128>>>((float*)d_out);
}

// round 9
// speedup vs baseline: 2.7920x; 1.1266x over previous
#include <cuda_runtime.h>
#include <cuda_bf16.h>
#include <cstdint>

#define Vn 30000
#define Kn 17
#define En 128
#define Hn 128
#define Bn 128
#define Tn 512
#define G4H 512   // 4*H

// ---------------- scratch (device globals; allocation-free) ----------------
// xp stored bf16, layout [dir][t][rank][b][128] with gate-permuted last dim:
//   c = (wid'<<4) | ((gate&2)<<2) | (a<<1) | (gate&1),  j = 32*rank + 4*wid' + a
__device__ __nv_bfloat16 g_xp_bf[(size_t)2 * Tn * 4 * Bn * 128];
__device__ __nv_bfloat16 g_hs_bf[(size_t)Tn * Bn * 2 * Hn];   // [t*B+b][256]
__device__ float g_em[(size_t)Bn * Tn * Kn];                  // [b][t][k]
__device__ float g_llh[Bn];
__device__ __nv_bfloat16 g_embed_bf[(size_t)Vn * En];
__device__ __nv_bfloat16 g_wih_bf[2 * (size_t)G4H * En];      // [dir][g][k]
__device__ __nv_bfloat16 g_wemit_bf[32 * 256];                // rows>=17 zero
__device__ float g_bias[2 * G4H];

__device__ __forceinline__ float tanha(float x) {
    float r; asm("tanh.approx.f32 %0,%1;" : "=f"(r) : "f"(x)); return r;
}
__device__ __forceinline__ float siga(float x) {
    return 0.5f * tanha(0.5f * x) + 0.5f;
}

// ================= Kernel 0: fp32 -> bf16 conversions =======================
__global__ __launch_bounds__(256) void k_cvt(
    const float* __restrict__ embed,
    const float* __restrict__ wf, const float* __restrict__ wb,
    const float* __restrict__ bihf, const float* __restrict__ bhhf,
    const float* __restrict__ bihb, const float* __restrict__ bhhb,
    const float* __restrict__ w_emit)
{
    int i = blockIdx.x * 256 + threadIdx.x;
    if (i < Vn * En / 2) {
        float2 v = ((const float2*)embed)[i];
        ((__nv_bfloat162*)g_embed_bf)[i] = __floats2bfloat162_rn(v.x, v.y);
    }
    if (i < G4H * En / 2) {
        float2 v = ((const float2*)wf)[i];
        ((__nv_bfloat162*)g_wih_bf)[i] = __floats2bfloat162_rn(v.x, v.y);
        float2 u = ((const float2*)wb)[i];
        ((__nv_bfloat162*)g_wih_bf)[G4H * En / 2 + i] = __floats2bfloat162_rn(u.x, u.y);
    }
    if (i < G4H) {
        g_bias[i] = bihf[i] + bhhf[i];
        g_bias[G4H + i] = bihb[i] + bhhb[i];
    }
    if (i < 32 * 128) {   // w_emit padded to 32 rows, bf16
        int row = i >> 7, col2 = i & 127;
        __nv_bfloat162 v;
        if (row < Kn) {
            v = __floats2bfloat162_rn(w_emit[row * 256 + 2 * col2],
                                      w_emit[row * 256 + 2 * col2 + 1]);
        } else {
            v = __floats2bfloat162_rn(0.0f, 0.0f);
        }
        ((__nv_bfloat162*)g_wemit_bf)[i] = v;
    }
}

// ---------------- mma / cluster helpers ----------------
__device__ __forceinline__ uint32_t smaddr(const void* p) {
    return (uint32_t)__cvta_generic_to_shared(p);
}
__device__ __forceinline__ void ldm4(uint32_t& r0, uint32_t& r1, uint32_t& r2, uint32_t& r3, uint32_t a) {
    asm volatile("ldmatrix.sync.aligned.m8n8.x4.shared.b16 {%0,%1,%2,%3},[%4];"
                 : "=r"(r0), "=r"(r1), "=r"(r2), "=r"(r3) : "r"(a));
}
__device__ __forceinline__ void mma16816(float* c, uint32_t a0, uint32_t a1, uint32_t a2, uint32_t a3,
                                         uint32_t b0, uint32_t b1) {
    asm volatile("mma.sync.aligned.m16n8k16.row.col.f32.bf16.bf16.f32 "
                 "{%0,%1,%2,%3},{%4,%5,%6,%7},{%8,%9},{%0,%1,%2,%3};"
                 : "+f"(c[0]), "+f"(c[1]), "+f"(c[2]), "+f"(c[3])
                 : "r"(a0), "r"(a1), "r"(a2), "r"(a3), "r"(b0), "r"(b1));
}
__device__ __forceinline__ uint32_t mapa_u32(uint32_t a, uint32_t rnk) {
    uint32_t d; asm("mapa.shared::cluster.u32 %0,%1,%2;" : "=r"(d) : "r"(a), "r"(rnk));
    return d;
}
__device__ __forceinline__ void mbar_init(uint32_t bar, uint32_t cnt) {
    asm volatile("mbarrier.init.shared.b64 [%0],%1;" :: "r"(bar), "r"(cnt) : "memory");
}
__device__ __forceinline__ void mbar_expect(uint32_t bar, uint32_t tx) {
    asm volatile("mbarrier.arrive.expect_tx.shared.b64 _,[%0],%1;" :: "r"(bar), "r"(tx) : "memory");
}
__device__ __forceinline__ void mbar_wait_cluster(uint32_t bar, uint32_t parity) {
    uint32_t done;
    do {
        asm volatile("{\n\t.reg .pred p;\n\t"
                     "mbarrier.try_wait.parity.acquire.cluster.shared::cta.b64 p,[%1],%2,0x989680;\n\t"
                     "selp.b32 %0,1,0,p;\n\t}"
                     : "=r"(done) : "r"(bar), "r"(parity) : "memory");
    } while (!done);
}
__device__ __forceinline__ void st_async_b64(uint32_t raddr, unsigned long long v, uint32_t rbar) {
    asm volatile("st.async.shared::cluster.mbarrier::complete_tx::bytes.b64 [%0],%1,[%2];"
                 :: "r"(raddr), "l"(v), "r"(rbar) : "memory");
}

#define ASTR 136   // bf16 elems per smem row (128 + 8 pad: conflict-free ldmatrix)

// ================= Kernel 1: input projection (tensor cores, permuted out) ==
// grid (8, 512): x = nt (dir*4+gate), y = t.
__global__ __launch_bounds__(256) void k_xp2(const int* __restrict__ ids)
{
    extern __shared__ char sm[];
    __nv_bfloat16* As = (__nv_bfloat16*)sm;                      // [128][136]
    __nv_bfloat16* Bs = (__nv_bfloat16*)(sm + 128 * ASTR * 2);   // [128][136]
    float* sbias = (float*)(sm + 2 * 128 * ASTR * 2);            // [128]

    const int t = blockIdx.y;
    const int nt = blockIdx.x;         // 0..7
    const int dir = nt >> 2;
    const int gate = nt & 3;
    const int gBase = gate * 128;
    const int tid = threadIdx.x;

    {
        int r = tid >> 1, half = tid & 1;
        int id = ids[r * Tn + t];
        const uint4* src = (const uint4*)(g_embed_bf + (size_t)id * En + half * 64);
        uint4* dst = (uint4*)(As + r * ASTR + half * 64);
#pragma unroll
        for (int i = 0; i < 8; i++) dst[i] = src[i];
        const uint4* wsrc = (const uint4*)(g_wih_bf + ((size_t)dir * G4H + gBase + r) * En + half * 64);
        uint4* wdst = (uint4*)(Bs + r * ASTR + half * 64);
#pragma unroll
        for (int i = 0; i < 8; i++) wdst[i] = wsrc[i];
    }
    if (tid < 128) sbias[tid] = g_bias[dir * G4H + gBase + tid];
    __syncthreads();

    const int wid = tid >> 5, lane = tid & 31;
    const int wm = (wid & 3) * 32;
    const int wn = (wid >> 2) * 64;

    float acc[2][8][4];
#pragma unroll
    for (int im = 0; im < 2; im++)
#pragma unroll
        for (int inn = 0; inn < 8; inn++)
#pragma unroll
            for (int r = 0; r < 4; r++) acc[im][inn][r] = 0.0f;

    const int lr = lane & 15, lc = lane >> 4;
#pragma unroll
    for (int kk = 0; kk < 8; kk++) {
        uint32_t a[2][4];
#pragma unroll
        for (int im = 0; im < 2; im++) {
            uint32_t ad = smaddr(As + (wm + im * 16 + lr) * ASTR + kk * 16 + lc * 8);
            ldm4(a[im][0], a[im][1], a[im][2], a[im][3], ad);
        }
        uint32_t b[4][4];
#pragma unroll
        for (int np = 0; np < 4; np++) {
            uint32_t ad = smaddr(Bs + (wn + np * 16 + lr) * ASTR + kk * 16 + lc * 8);
            ldm4(b[np][0], b[np][1], b[np][2], b[np][3], ad);
        }
#pragma unroll
        for (int im = 0; im < 2; im++)
#pragma unroll
            for (int inn = 0; inn < 8; inn++) {
                int np = inn >> 1, hf = inn & 1;
                uint32_t bb0 = hf ? b[np][1] : b[np][0];
                uint32_t bb1 = hf ? b[np][3] : b[np][2];
                mma16816(acc[im][inn], a[im][0], a[im][1], a[im][2], a[im][3], bb0, bb1);
            }
    }

    // epilogue: bias, bf16, permuted scatter to [dir][trow][rank][b][c]
    const int trow = dir ? (Tn - 1 - t) : t;
#pragma unroll
    for (int im = 0; im < 2; im++)
#pragma unroll
        for (int inn = 0; inn < 8; inn++) {
            int gl = wn + inn * 8 + 2 * (lane & 3);       // j (even)
            float bx = sbias[gl], by = sbias[gl + 1];
            int rho = gl >> 5, jl = gl & 31;
            int widp = jl >> 2, aa = jl & 3;
            int cpos = (widp << 4) | ((gate & 2) << 2) | (aa << 1) | (gate & 1);
            int row0 = wm + im * 16 + (lane >> 2);
            size_t base = (((size_t)(dir * Tn + trow) * 4 + rho) * Bn) * 128;
            g_xp_bf[base + (size_t)row0 * 128 + cpos]     = __float2bfloat16(acc[im][inn][0] + bx);
            g_xp_bf[base + (size_t)row0 * 128 + cpos + 2] = __float2bfloat16(acc[im][inn][1] + by);
            g_xp_bf[base + (size_t)(row0 + 8) * 128 + cpos]     = __float2bfloat16(acc[im][inn][2] + bx);
            g_xp_bf[base + (size_t)(row0 + 8) * 128 + cpos + 2] = __float2bfloat16(acc[im][inn][3] + by);
        }
}

// ================= Kernel 2: cluster-4 j-split BiLSTM recurrence ============
// Cluster of 4 CTAs = one (dir, 16-batch group). CTA rank owns j-range
// [32*rank, 32*rank+32): all 4 gates (W rows permuted so each MMA fragment
// holds i,f,g,o of one (b,j) in-thread). Pointwise fully in registers.
// h exchange: staged into contiguous smem, then 128 threads send b64
// messages to 3 peers (384 msgs vs 1024 scalar b32); own slice written
// locally. TWO alternating mbarriers (step t uses bars[t&1], parity
// (t>>1)&1) keep tx-byte attribution sound.
__global__ __launch_bounds__(256, 1) __cluster_dims__(4, 1, 1)
void k_lstm6(const float* __restrict__ whhf, const float* __restrict__ whhb)
{
    __shared__ __nv_bfloat16 Wsm[128 * ASTR];
    __shared__ __nv_bfloat16 Hsm[2][16 * ASTR];
    __shared__ __align__(16) uint32_t Sg[256];   // staging [16 rows][16 u32]
    __shared__ __align__(8) unsigned long long hbar_s[2];

    const int cid = blockIdx.x >> 2;
    const int rank = blockIdx.x & 3;
    const int dir = cid >> 3;
    const int b0 = (cid & 7) * 16;
    const float* whh = dir ? whhb : whhf;
    const int tid = threadIdx.x;
    const int wid = tid >> 5, lane = tid & 31;

    // ---- load my 128 permuted W_hh rows as bf16 ----
    {
        int c = tid >> 1, half = tid & 1;
        int gate = (c & 1) + 2 * ((c >> 3) & 1);
        int jl = 4 * (c >> 4) + ((c & 7) >> 1);
        int grow = gate * 128 + 32 * rank + jl;
        const float2* src = (const float2*)(whh + (size_t)grow * Hn + half * 64);
        __nv_bfloat162* dst = (__nv_bfloat162*)(Wsm + c * ASTR + half * 64);
#pragma unroll
        for (int i = 0; i < 32; i++) {
            float2 v = src[i];
            dst[i] = __floats2bfloat162_rn(v.x, v.y);
        }
    }
    for (int i = tid; i < 2 * 16 * ASTR / 2; i += 256) ((uint32_t*)Hsm)[i] = 0u;

    const uint32_t hbar0 = smaddr(&hbar_s[0]);
    const uint32_t hbar1 = smaddr(&hbar_s[1]);
    if (tid == 0) {
        mbar_init(hbar0, 1);
        mbar_init(hbar1, 1);
        mbar_expect(hbar0, 3072);   // phase 0 of barrier 0 (3 peers x 1KB)
        mbar_expect(hbar1, 3072);   // phase 0 of barrier 1
    }
    __syncthreads();
    asm volatile("barrier.cluster.arrive.aligned;" ::: "memory");
    asm volatile("barrier.cluster.wait.aligned;" ::: "memory");

    // ---- hoist W fragments (step-invariant) ----
    const int lr = lane & 15, lc = lane >> 4;
    uint32_t bw[8][4];
#pragma unroll
    for (int kk = 0; kk < 8; kk++)
        ldm4(bw[kk][0], bw[kk][1], bw[kk][2], bw[kk][3],
             smaddr(Wsm + (16 * wid + lr) * ASTR + kk * 16 + lc * 8));

    // ---- thread coords & precomputed addresses ----
    const int a = lane & 3, r = lane >> 2;
    const int cb = 16 * wid + 2 * a;
    const int j = 32 * rank + 4 * wid + a;
    const int destrow = (a & 1) ? (r + 8) : r;
    const int destcol = (a & 1) ? (j - 1) : j;   // even, in [32*rank, 32*rank+32)
    // own-slice write pointers (local stores, no message)
    uint32_t* ownH[2];
    ownH[0] = (uint32_t*)&Hsm[0][destrow * ASTR + destcol];
    ownH[1] = (uint32_t*)&Hsm[1][destrow * ASTR + destcol];
    const int sgIdx = destrow * 16 + ((destcol >> 1) & 15);

    // sender thread (tid<128) remote addresses: row=tid>>3, pair=tid&7
    const int srow = tid >> 3, spr = tid & 7;
    uint32_t aR[2][4], barH[2][4];
#pragma unroll
    for (int buf = 0; buf < 2; buf++) {
        uint32_t la = smaddr(&Hsm[buf][srow * ASTR + 32 * rank + 4 * spr]);
#pragma unroll
        for (int p = 0; p < 4; p++) aR[buf][p] = mapa_u32(la, p);
    }
#pragma unroll
    for (int p = 0; p < 4; p++) {
        barH[0][p] = mapa_u32(hbar0, p);
        barH[1][p] = mapa_u32(hbar1, p);
    }

    const uint32_t* xb = (const uint32_t*)g_xp_bf
        + ((size_t)dir * Tn * 4 + rank) * Bn * 64 + (size_t)(b0 + r) * 64 + (cb >> 1);
    const size_t tstep = 4 * (size_t)Bn * 64;   // u32 per t

    const uint32_t ghs_ofs = (uint32_t)(((b0 + destrow) * 256 + dir * 128 + destcol) >> 1);
    uint32_t* ghs = (uint32_t*)g_hs_bf;

    uint32_t v00 = xb[0], v01 = xb[4], v10 = xb[512], v11 = xb[516];
    float creg0 = 0.0f, creg1 = 0.0f;

    for (int t = 0; t < Tn; t++) {
        uint32_t n00, n01, n10, n11;
        if (t + 1 < Tn) {
            const uint32_t* p = xb + (size_t)(t + 1) * tstep;
            n00 = p[0]; n01 = p[4]; n10 = p[512]; n11 = p[516];
        }
        // acc init from permuted xp: acc0={i,f}(r),(r+8); acc1={g,o}(r),(r+8)
        float acc0[4], acc1[4];
        {
            __nv_bfloat162 u;
            u = *(__nv_bfloat162*)&v00; acc0[0] = __bfloat162float(u.x); acc0[1] = __bfloat162float(u.y);
            u = *(__nv_bfloat162*)&v10; acc0[2] = __bfloat162float(u.x); acc0[3] = __bfloat162float(u.y);
            u = *(__nv_bfloat162*)&v01; acc1[0] = __bfloat162float(u.x); acc1[1] = __bfloat162float(u.y);
            u = *(__nv_bfloat162*)&v11; acc1[2] = __bfloat162float(u.x); acc1[3] = __bfloat162float(u.y);
        }
        // GEMM from current h buffer
        const __nv_bfloat16* hb = Hsm[t & 1];
#pragma unroll
        for (int kk = 0; kk < 8; kk++) {
            uint32_t a0, a1, a2, a3;
            ldm4(a0, a1, a2, a3, smaddr(hb + lr * ASTR + kk * 16 + lc * 8));
            mma16816(acc0, a0, a1, a2, a3, bw[kk][0], bw[kk][2]);
            mma16816(acc1, a0, a1, a2, a3, bw[kk][1], bw[kk][3]);
        }
        // pointwise in registers: (i,f,g,o) at (b=r / r+8, j)
        creg0 = siga(acc0[1]) * creg0 + siga(acc0[0]) * tanha(acc1[0]);
        float h0 = siga(acc1[1]) * tanha(creg0);
        creg1 = siga(acc0[3]) * creg1 + siga(acc0[2]) * tanha(acc1[2]);
        float h1 = siga(acc1[3]) * tanha(creg1);

        float h0p = __shfl_xor_sync(0xffffffffu, h0, 1);
        float h1p = __shfl_xor_sync(0xffffffffu, h1, 1);
        __nv_bfloat162 pk = (a & 1) ? __floats2bfloat162_rn(h1p, h1)
                                    : __floats2bfloat162_rn(h0, h0p);
        uint32_t val = *(uint32_t*)&pk;

        int trow = dir ? (Tn - 1 - t) : t;
        ghs[(uint32_t)trow * 16384 + ghs_ofs] = val;

        if (t + 1 < Tn) {
            const int bb = t & 1;               // barrier for this step
            const int nb = (t + 1) & 1;         // h buffer for next step
            // own slice: local store; remote slices: staged coalesced send
            *ownH[nb] = val;
            Sg[sgIdx] = val;
            __syncthreads();
            if (tid < 128) {
                uint2 v2 = ((const uint2*)Sg)[tid];
                unsigned long long pv = ((unsigned long long)v2.y << 32) | v2.x;
#pragma unroll
                for (int p = 0; p < 4; p++)
                    if (p != rank) st_async_b64(aR[nb][p], pv, barH[bb][p]);
            }
            mbar_wait_cluster(bb ? hbar1 : hbar0, (t >> 1) & 1);
            if (tid == 0) mbar_expect(bb ? hbar1 : hbar0, 3072);
            v00 = n00; v01 = n01; v10 = n10; v11 = n11;
        }
    }
}

// ================= Kernel 3: emissions via tensor cores =====================
// em[b][t][k] = h_bf[bt] . w_emit_bf[k] + b_emit[k];  block = 64 bt rows.
#define ESTR 264
__global__ __launch_bounds__(128) void k_emit2(const float* __restrict__ b_emit)
{
    extern __shared__ char sm[];
    __nv_bfloat16* As = (__nv_bfloat16*)sm;                     // [64][264]
    __nv_bfloat16* Bs = (__nv_bfloat16*)(sm + 64 * ESTR * 2);   // [32][264]
    float* sbias = (float*)(sm + (64 + 32) * ESTR * 2);         // [32]

    const int tid = threadIdx.x;
    const int bt0 = blockIdx.x * 64;

    {
        int row = tid >> 1, half = tid & 1;
        const uint4* src = (const uint4*)(g_hs_bf + (size_t)(bt0 + row) * 256 + half * 128);
        uint4* dst = (uint4*)(As + row * ESTR + half * 128);
#pragma unroll
        for (int i = 0; i < 16; i++) dst[i] = src[i];
        if (tid < 64) {
            const uint4* ws = (const uint4*)(g_wemit_bf + (size_t)row * 256 + half * 128);
            uint4* wd = (uint4*)(Bs + row * ESTR + half * 128);
#pragma unroll
            for (int i = 0; i < 16; i++) wd[i] = ws[i];
        }
    }
    if (tid < 32) sbias[tid] = (tid < Kn) ? b_emit[tid] : 0.0f;
    __syncthreads();

    const int wid = tid >> 5, lane = tid & 31;
    const int lr = lane & 15, lc = lane >> 4;

    float acc[3][4];
#pragma unroll
    for (int nt = 0; nt < 3; nt++)
#pragma unroll
        for (int q = 0; q < 4; q++) acc[nt][q] = 0.0f;

#pragma unroll
    for (int kk = 0; kk < 16; kk++) {
        uint32_t a0, a1, a2, a3;
        ldm4(a0, a1, a2, a3, smaddr(As + (16 * wid + lr) * ESTR + kk * 16 + lc * 8));
        uint32_t b0[4], b1[4];
        ldm4(b0[0], b0[1], b0[2], b0[3], smaddr(Bs + lr * ESTR + kk * 16 + lc * 8));
        ldm4(b1[0], b1[1], b1[2], b1[3], smaddr(Bs + (16 + lr) * ESTR + kk * 16 + lc * 8));
        mma16816(acc[0], a0, a1, a2, a3, b0[0], b0[2]);   // n 0..7
        mma16816(acc[1], a0, a1, a2, a3, b0[1], b0[3]);   // n 8..15
        mma16816(acc[2], a0, a1, a2, a3, b1[0], b1[2]);   // n 16..23
    }

    const int r = lane >> 2;
#pragma unroll
    for (int nt = 0; nt < 3; nt++) {
#pragma unroll
        for (int q = 0; q < 4; q++) {
            int n = 8 * nt + 2 * (lane & 3) + (q & 1);
            if (n >= Kn) continue;
            int bt = bt0 + 16 * wid + r + ((q >> 1) ? 8 : 0);
            int t = bt >> 7, b = bt & 127;
            g_em[((size_t)b * Tn + t) * Kn + n] = acc[nt][q] + sbias[n];
        }
    }
}

// ================= Kernel 4: CRF (linear-domain forward), 4 batches/warp ====
__global__ void k_crf2(const int* __restrict__ tags,
                       const float* __restrict__ start_t,
                       const float* __restrict__ end_t,
                       const float* __restrict__ trans)
{
    const int lane = threadIdx.x;
    const int laneC = (lane < Kn) ? lane : 0;
    int bidx[4];
    const float* em[4];
    const int* tg[4];
#pragma unroll
    for (int q = 0; q < 4; q++) {
        bidx[q] = blockIdx.x + 32 * q;
        em[q] = g_em + (size_t)bidx[q] * Tn * Kn;
        tg[q] = tags + bidx[q] * Tn;
    }

    float T[Kn];
#pragma unroll
    for (int i = 0; i < Kn; i++)
        T[i] = (lane < Kn) ? __expf(trans[i * Kn + lane]) : 0.0f;

    // ---- numerator (gold-path score): parallel over t ----
    float sc[4];
#pragma unroll
    for (int q = 0; q < 4; q++) {
        float s = 0.0f;
        for (int t = lane + 1; t < Tn; t += 32)
            s += trans[tg[q][t - 1] * Kn + tg[q][t]] + em[q][(size_t)t * Kn + tg[q][t]];
#pragma unroll
        for (int off = 16; off; off >>= 1) s += __shfl_xor_sync(0xffffffffu, s, off);
        s += start_t[tg[q][0]] + em[q][tg[q][0]] + end_t[tg[q][Tn - 1]];
        sc[q] = s;
    }

    // ---- denominator: linear-domain forward with periodic renorm ----
    float A[4], la[4], ec[4];
#pragma unroll
    for (int q = 0; q < 4; q++) {
        A[q] = (lane < Kn) ? __expf(start_t[lane] + em[q][lane]) : 0.0f;
        la[q] = 0.0f;
        ec[q] = em[q][Kn + laneC];
    }

    for (int t = 1; t < Tn; t++) {
        float en[4];
        if (t + 1 < Tn) {
#pragma unroll
            for (int q = 0; q < 4; q++) en[q] = em[q][(size_t)(t + 1) * Kn + laneC];
        }
        float s0 = 0.f, s1 = 0.f, s2 = 0.f, s3 = 0.f;
#pragma unroll
        for (int i = 0; i < Kn; i++) {
            float a0 = __shfl_sync(0xffffffffu, A[0], i);
            float a1 = __shfl_sync(0xffffffffu, A[1], i);
            float a2 = __shfl_sync(0xffffffffu, A[2], i);
            float a3 = __shfl_sync(0xffffffffu, A[3], i);
            s0 += a0 * T[i]; s1 += a1 * T[i]; s2 += a2 * T[i]; s3 += a3 * T[i];
        }
        A[0] = s0 * __expf(ec[0]);
        A[1] = s1 * __expf(ec[1]);
        A[2] = s2 * __expf(ec[2]);
        A[3] = s3 * __expf(ec[3]);
        if ((t & 3) == 3) {
#pragma unroll
            for (int q = 0; q < 4; q++) {
                float m = A[q];
#pragma unroll
                for (int off = 16; off; off >>= 1)
                    m = fmaxf(m, __shfl_xor_sync(0xffffffffu, m, off));
                la[q] += __logf(m);
                A[q] = __fdividef(A[q], m);
            }
        }
        if (t + 1 < Tn) {
#pragma unroll
            for (int q = 0; q < 4; q++) ec[q] = en[q];
        }
    }

    float Ee = (lane < Kn) ? __expf(end_t[lane]) : 0.0f;
#pragma unroll
    for (int q = 0; q < 4; q++) {
        float x = A[q] * Ee;
#pragma unroll
        for (int off = 16; off; off >>= 1) x += __shfl_xor_sync(0xffffffffu, x, off);
        float logZ = __logf(x) + la[q];
        if (lane == 0) g_llh[bidx[q]] = sc[q] - logZ;
    }
}

// ================= Kernel 5: final mean =====================================
__global__ void k_reduce(float* __restrict__ out)
{
    const int tid = threadIdx.x; // 128
    float v = g_llh[tid];
#pragma unroll
    for (int off = 16; off; off >>= 1) v += __shfl_xor_sync(0xffffffffu, v, off);
    __shared__ float s[4];
    if ((tid & 31) == 0) s[tid >> 5] = v;
    __syncthreads();
    if (tid == 0) out[0] = -(s[0] + s[1] + s[2] + s[3]) / (float)Bn;
}

// ============================================================================
extern "C" void kernel_launch(void* const* d_in, const int* in_sizes, int n_in,
                              void* d_out, int out_size)
{
    const int*   ids     = (const int*)d_in[0];
    const int*   tags    = (const int*)d_in[1];
    // d_in[2] = mask: all-true for this problem; intentionally unused.
    const float* embed   = (const float*)d_in[3];
    const float* w_ih_f  = (const float*)d_in[4];
    const float* w_hh_f  = (const float*)d_in[5];
    const float* b_ih_f  = (const float*)d_in[6];
    const float* b_hh_f  = (const float*)d_in[7];
    const float* w_ih_b  = (const float*)d_in[8];
    const float* w_hh_b  = (const float*)d_in[9];
    const float* b_ih_b  = (const float*)d_in[10];
    const float* b_hh_b  = (const float*)d_in[11];
    const float* w_emit  = (const float*)d_in[12];
    const float* b_emit  = (const float*)d_in[13];
    const float* start_t = (const float*)d_in[14];
    const float* end_t   = (const float*)d_in[15];
    const float* trans   = (const float*)d_in[16];

    const int SMEM_XP2  = 2 * 128 * ASTR * 2 + 512;          // 70,144 B
    const int SMEM_EMIT = (64 + 32) * ESTR * 2 + 128;        // 50,816 B
    cudaFuncSetAttribute(k_xp2,   cudaFuncAttributeMaxDynamicSharedMemorySize, SMEM_XP2);
    cudaFuncSetAttribute(k_emit2, cudaFuncAttributeMaxDynamicSharedMemorySize, SMEM_EMIT);

    k_cvt<<<Vn * En / 2 / 256, 256>>>(embed, w_ih_f, w_ih_b,
                                      b_ih_f, b_hh_f, b_ih_b, b_hh_b, w_emit);
    k_xp2<<<dim3(8, 512), 256, SMEM_XP2>>>(ids);
    k_lstm6<<<64, 256>>>(w_hh_f, w_hh_b);
    k_emit2<<<1024, 128, SMEM_EMIT>>>(b_emit);
    k_crf2<<<32, 32>>>(tags, start_t, end_t, trans);
    k_reduce<<<1, 128>>>((float*)d_out);
}